// round 1
// baseline (speedup 1.0000x reference)
#include <cuda_runtime.h>
#include <math_constants.h>
#include <math.h>

#define B_   4
#define S_   2048
#define H_   12
#define DM_  768
#define MROWS (B_*S_)   // 8192

// ---------------- scratch (static device arrays; no allocation) ----------------
__device__ float g_Cq [MROWS*128];
__device__ float g_Ckv[MROWS*128];
__device__ float g_qn [MROWS*768];
__device__ float g_kn [MROWS*768];
__device__ float g_qr [MROWS*768];
__device__ float g_kr [MROWS*768];
__device__ float g_v  [MROWS*1536];
__device__ float g_q  [(size_t)B_*H_*S_*128];
__device__ float g_k  [(size_t)B_*H_*S_*128];
__device__ float g_vh [(size_t)B_*H_*S_*128];
__device__ float g_o  [MROWS*1536];

// ---------------- generic SGEMM: Y[M,N] = X[M,K] @ W[N,K]^T + bias ----------------
#define GBM 128
#define GBN 128
#define GBK 16

__global__ __launch_bounds__(256)
void sgemm_bias(const float* __restrict__ X, const float* __restrict__ W,
                const float* __restrict__ bias, float* __restrict__ Y,
                int M, int N, int K)
{
    __shared__ float As[GBK][GBM + 4];
    __shared__ float Bs[GBK][GBN + 4];

    const int tid = threadIdx.x;
    const int tx = tid & 15;      // col group
    const int ty = tid >> 4;      // row group
    const int row0 = blockIdx.y * GBM;
    const int col0 = blockIdx.x * GBN;

    float acc[8][8];
#pragma unroll
    for (int i = 0; i < 8; i++)
#pragma unroll
        for (int j = 0; j < 8; j++) acc[i][j] = 0.f;

    for (int k0 = 0; k0 < K; k0 += GBK) {
#pragma unroll
        for (int it = 0; it < 2; it++) {
            int idx = tid + it * 256;            // 512 float4 per tile
            int r = idx >> 2;
            int c4 = (idx & 3) << 2;
            float4 va = *(const float4*)&X[(size_t)(row0 + r) * K + k0 + c4];
            As[c4 + 0][r] = va.x; As[c4 + 1][r] = va.y;
            As[c4 + 2][r] = va.z; As[c4 + 3][r] = va.w;
            float4 vb = *(const float4*)&W[(size_t)(col0 + r) * K + k0 + c4];
            Bs[c4 + 0][r] = vb.x; Bs[c4 + 1][r] = vb.y;
            Bs[c4 + 2][r] = vb.z; Bs[c4 + 3][r] = vb.w;
        }
        __syncthreads();

#pragma unroll
        for (int kk = 0; kk < GBK; kk++) {
            float a[8], b[8];
            float4 a0 = *(const float4*)&As[kk][ty * 8];
            float4 a1 = *(const float4*)&As[kk][ty * 8 + 4];
            a[0]=a0.x; a[1]=a0.y; a[2]=a0.z; a[3]=a0.w;
            a[4]=a1.x; a[5]=a1.y; a[6]=a1.z; a[7]=a1.w;
            float4 b0 = *(const float4*)&Bs[kk][tx * 8];
            float4 b1 = *(const float4*)&Bs[kk][tx * 8 + 4];
            b[0]=b0.x; b[1]=b0.y; b[2]=b0.z; b[3]=b0.w;
            b[4]=b1.x; b[5]=b1.y; b[6]=b1.z; b[7]=b1.w;
#pragma unroll
            for (int i = 0; i < 8; i++)
#pragma unroll
                for (int j = 0; j < 8; j++)
                    acc[i][j] = fmaf(a[i], b[j], acc[i][j]);
        }
        __syncthreads();
    }

#pragma unroll
    for (int i = 0; i < 8; i++) {
        int m = row0 + ty * 8 + i;
#pragma unroll
        for (int j = 0; j < 8; j += 4) {
            int n = col0 + tx * 8 + j;
            float4 o;
            o.x = acc[i][j + 0] + bias[n + 0];
            o.y = acc[i][j + 1] + bias[n + 1];
            o.z = acc[i][j + 2] + bias[n + 2];
            o.w = acc[i][j + 3] + bias[n + 3];
            *(float4*)&Y[(size_t)m * N + n] = o;
        }
    }
}

// ---------------- rope (full 768-dim, 384 pairs) + flat-concat head scatter ----------------
// Reference semantics: head h of q/k = flat slice [h*128,(h+1)*128) of
// [nope(768) | roped_rope(768)]. v head h = v[h*128:(h+1)*128).
__global__ void rope_concat_kernel(const float* __restrict__ qn, const float* __restrict__ qr,
                                   const float* __restrict__ kn, const float* __restrict__ kr,
                                   const float* __restrict__ vv,
                                   float* __restrict__ q, float* __restrict__ k,
                                   float* __restrict__ vh)
{
    int t = blockIdx.x * blockDim.x + threadIdx.x;
    if (t >= MROWS * 384) return;
    int i  = t % 384;          // frequency pair index over 768 dims
    int bs = t / 384;          // b*S + s
    int s  = bs % S_;
    int b  = bs / S_;

    // inv_freq = theta^(-(2i)/768); compute in double for a clean fp32 value
    float inv = (float)exp(-((double)(2 * i) / 768.0) * log(10000.0));
    float ang = (float)s * inv;
    float c = cosf(ang), sn = sinf(ang);

    int f  = 2 * i;          // nope flat index
    int f2 = 768 + 2 * i;    // rope flat index in concat space
    int h  = f  >> 7, d  = f  & 127;
    int h2 = f2 >> 7, d2 = f2 & 127;
    size_t dstN = (((size_t)(b * H_ + h )) * S_ + s) * 128 + d;
    size_t dstR = (((size_t)(b * H_ + h2)) * S_ + s) * 128 + d2;

    // q
    {
        const float* nsrc = qn + (size_t)bs * 768;
        const float* rsrc = qr + (size_t)bs * 768;
        float e = rsrc[f], o = rsrc[f + 1];
        q[dstN]     = nsrc[f];
        q[dstN + 1] = nsrc[f + 1];
        q[dstR]     = e * c - o * sn;
        q[dstR + 1] = e * sn + o * c;
    }
    // k
    {
        const float* nsrc = kn + (size_t)bs * 768;
        const float* rsrc = kr + (size_t)bs * 768;
        float e = rsrc[f], o = rsrc[f + 1];
        k[dstN]     = nsrc[f];
        k[dstN + 1] = nsrc[f + 1];
        k[dstR]     = e * c - o * sn;
        k[dstR + 1] = e * sn + o * c;
    }
    // v scatter: 4 elems per thread (384*4 = 1536)
    {
        const float* src = vv + (size_t)bs * 1536 + 4 * i;
#pragma unroll
        for (int u = 0; u < 4; u++) {
            int fv = 4 * i + u;
            int hv = fv >> 7, dv = fv & 127;
            vh[(((size_t)(b * H_ + hv)) * S_ + s) * 128 + dv] = src[u];
        }
    }
}

// ---------------- flash attention (fp32, causal), 64x64 tiles ----------------
// q,k,v: [B*H][S][128]; output written to o in [B,S,H*128] layout for the final GEMM.
#define ATT_SMEM ((64*128 + 128*65 + 64*128 + 64*68) * 4)

__global__ __launch_bounds__(256, 1)
void attn_kernel(const float* __restrict__ q, const float* __restrict__ k,
                 const float* __restrict__ v, float* __restrict__ o)
{
    extern __shared__ float sm[];
    float* Qs  = sm;                   // [64][128]
    float* Kst = Qs  + 64 * 128;       // [128][65]  (transposed K tile)
    float* Vs  = Kst + 128 * 65;       // [64][128]
    float* Ps  = Vs  + 64 * 128;       // [64][68]

    const int tid = threadIdx.x;
    const int tx = tid & 15;           // 16 col groups
    const int ty = tid >> 4;           // 16 row groups
    const int qt = blockIdx.x;
    const int bh = blockIdx.y;
    const int b = bh / H_, h = bh % H_;
    const size_t base = (size_t)bh * S_ * 128;
    const float scale = 0.08838834764831845f;   // 1/sqrt(128)

    // load Q tile once
    {
        const float4* src = (const float4*)(q + base + (size_t)qt * 64 * 128);
        float4* dst = (float4*)Qs;
#pragma unroll
        for (int it = 0; it < 8; it++) dst[tid + it * 256] = src[tid + it * 256];
    }

    float acc[4][8];
#pragma unroll
    for (int i = 0; i < 4; i++)
#pragma unroll
        for (int c = 0; c < 8; c++) acc[i][c] = 0.f;
    float m_i[4] = {-CUDART_INF_F, -CUDART_INF_F, -CUDART_INF_F, -CUDART_INF_F};
    float l_i[4] = {0.f, 0.f, 0.f, 0.f};

    for (int kt = 0; kt <= qt; kt++) {
        __syncthreads();   // previous-iter Ps/Vs reads done (also covers Q load on iter 0)
        // load K tile transposed + V tile
        {
            const float4* ks = (const float4*)(k + base + (size_t)kt * 64 * 128);
            const float4* vs = (const float4*)(v + base + (size_t)kt * 64 * 128);
            float4* vd = (float4*)Vs;
#pragma unroll
            for (int it = 0; it < 8; it++) {
                int idx = tid + it * 256;
                int r = idx >> 5;
                int c4 = (idx & 31) << 2;
                float4 kv = ks[idx];
                Kst[(c4 + 0) * 65 + r] = kv.x;
                Kst[(c4 + 1) * 65 + r] = kv.y;
                Kst[(c4 + 2) * 65 + r] = kv.z;
                Kst[(c4 + 3) * 65 + r] = kv.w;
                vd[idx] = vs[idx];
            }
        }
        __syncthreads();

        // S = Q @ K^T (4x4 fragment per thread)
        float sv[4][4];
#pragma unroll
        for (int i = 0; i < 4; i++)
#pragma unroll
            for (int j = 0; j < 4; j++) sv[i][j] = 0.f;
#pragma unroll 4
        for (int kk = 0; kk < 128; kk++) {
            float a[4], bb[4];
#pragma unroll
            for (int i = 0; i < 4; i++) a[i] = Qs[(ty * 4 + i) * 128 + kk];
#pragma unroll
            for (int j = 0; j < 4; j++) bb[j] = Kst[kk * 65 + tx * 4 + j];
#pragma unroll
            for (int i = 0; i < 4; i++)
#pragma unroll
                for (int j = 0; j < 4; j++)
                    sv[i][j] = fmaf(a[i], bb[j], sv[i][j]);
        }
        // scale + causal mask (diagonal tile only)
#pragma unroll
        for (int i = 0; i < 4; i++)
#pragma unroll
            for (int j = 0; j < 4; j++) {
                sv[i][j] *= scale;
                if (kt == qt && (tx * 4 + j) > (ty * 4 + i)) sv[i][j] = -CUDART_INF_F;
            }

        // online softmax update
        float fac[4];
#pragma unroll
        for (int i = 0; i < 4; i++) {
            float mx = fmaxf(fmaxf(sv[i][0], sv[i][1]), fmaxf(sv[i][2], sv[i][3]));
#pragma unroll
            for (int off = 8; off; off >>= 1)
                mx = fmaxf(mx, __shfl_xor_sync(0xffffffffu, mx, off, 16));
            float mnew = fmaxf(m_i[i], mx);
            fac[i] = __expf(m_i[i] - mnew);
            m_i[i] = mnew;
            float rs = 0.f;
#pragma unroll
            for (int j = 0; j < 4; j++) {
                float p = __expf(sv[i][j] - mnew);
                sv[i][j] = p;
                rs += p;
            }
#pragma unroll
            for (int off = 8; off; off >>= 1)
                rs += __shfl_xor_sync(0xffffffffu, rs, off, 16);
            l_i[i] = l_i[i] * fac[i] + rs;
#pragma unroll
            for (int c = 0; c < 8; c++) acc[i][c] *= fac[i];
            // store P row fragment
            float4 st = make_float4(sv[i][0], sv[i][1], sv[i][2], sv[i][3]);
            *(float4*)&Ps[(ty * 4 + i) * 68 + tx * 4] = st;
        }
        __syncthreads();

        // O += P @ V
#pragma unroll 2
        for (int j = 0; j < 64; j++) {
            float a[4];
#pragma unroll
            for (int i = 0; i < 4; i++) a[i] = Ps[(ty * 4 + i) * 68 + j];
            float4 b0 = *(const float4*)&Vs[j * 128 + tx * 8];
            float4 b1 = *(const float4*)&Vs[j * 128 + tx * 8 + 4];
#pragma unroll
            for (int i = 0; i < 4; i++) {
                acc[i][0] = fmaf(a[i], b0.x, acc[i][0]);
                acc[i][1] = fmaf(a[i], b0.y, acc[i][1]);
                acc[i][2] = fmaf(a[i], b0.z, acc[i][2]);
                acc[i][3] = fmaf(a[i], b0.w, acc[i][3]);
                acc[i][4] = fmaf(a[i], b1.x, acc[i][4]);
                acc[i][5] = fmaf(a[i], b1.y, acc[i][5]);
                acc[i][6] = fmaf(a[i], b1.z, acc[i][6]);
                acc[i][7] = fmaf(a[i], b1.w, acc[i][7]);
            }
        }
    }

    // epilogue: normalize and write to [B,S,H*128]
#pragma unroll
    for (int i = 0; i < 4; i++) {
        int srow = qt * 64 + ty * 4 + i;
        float invl = 1.0f / l_i[i];
        size_t off = ((size_t)(b * S_ + srow)) * 1536 + h * 128 + tx * 8;
        float4 o0 = make_float4(acc[i][0]*invl, acc[i][1]*invl, acc[i][2]*invl, acc[i][3]*invl);
        float4 o1 = make_float4(acc[i][4]*invl, acc[i][5]*invl, acc[i][6]*invl, acc[i][7]*invl);
        *(float4*)&o[off]     = o0;
        *(float4*)&o[off + 4] = o1;
    }
}

// ---------------- launch ----------------
extern "C" void kernel_launch(void* const* d_in, const int* in_sizes, int n_in,
                              void* d_out, int out_size)
{
    const float* x         = (const float*)d_in[0];
    // d_in[1] = token_positions (== arange(S); value used implicitly as s index)
    const float* W_dkv     = (const float*)d_in[2];
    const float* b_dkv     = (const float*)d_in[3];
    const float* W_dq      = (const float*)d_in[4];
    const float* b_dq      = (const float*)d_in[5];
    const float* W_uk_nope = (const float*)d_in[6];
    const float* b_uk_nope = (const float*)d_in[7];
    const float* W_uv      = (const float*)d_in[8];
    const float* b_uv      = (const float*)d_in[9];
    const float* W_uq_nope = (const float*)d_in[10];
    const float* b_uq_nope = (const float*)d_in[11];
    const float* W_uq_rope = (const float*)d_in[12];
    const float* b_uq_rope = (const float*)d_in[13];
    const float* W_uk_rope = (const float*)d_in[14];
    const float* b_uk_rope = (const float*)d_in[15];
    const float* W_o       = (const float*)d_in[16];
    const float* b_o       = (const float*)d_in[17];
    float* out = (float*)d_out;

    float *Cq, *Ckv, *qn, *kn, *qr, *kr, *vv, *q, *k, *vh, *o;
    cudaGetSymbolAddress((void**)&Cq,  g_Cq);
    cudaGetSymbolAddress((void**)&Ckv, g_Ckv);
    cudaGetSymbolAddress((void**)&qn,  g_qn);
    cudaGetSymbolAddress((void**)&kn,  g_kn);
    cudaGetSymbolAddress((void**)&qr,  g_qr);
    cudaGetSymbolAddress((void**)&kr,  g_kr);
    cudaGetSymbolAddress((void**)&vv,  g_v);
    cudaGetSymbolAddress((void**)&q,   g_q);
    cudaGetSymbolAddress((void**)&k,   g_k);
    cudaGetSymbolAddress((void**)&vh,  g_vh);
    cudaGetSymbolAddress((void**)&o,   g_o);

    cudaFuncSetAttribute(attn_kernel, cudaFuncAttributeMaxDynamicSharedMemorySize, ATT_SMEM);

    dim3 t(256);
    // latent projections
    sgemm_bias<<<dim3(1, 64), t>>>(x,   W_dq,      b_dq,      Cq,  MROWS, 128,  DM_);
    sgemm_bias<<<dim3(1, 64), t>>>(x,   W_dkv,     b_dkv,     Ckv, MROWS, 128,  DM_);
    // up projections
    sgemm_bias<<<dim3(6, 64), t>>>(Cq,  W_uq_nope, b_uq_nope, qn,  MROWS, 768,  128);
    sgemm_bias<<<dim3(6, 64), t>>>(Ckv, W_uk_nope, b_uk_nope, kn,  MROWS, 768,  128);
    sgemm_bias<<<dim3(6, 64), t>>>(Cq,  W_uq_rope, b_uq_rope, qr,  MROWS, 768,  128);
    sgemm_bias<<<dim3(12,64), t>>>(Ckv, W_uv,      b_uv,      vv,  MROWS, 1536, 128);
    sgemm_bias<<<dim3(6, 64), t>>>(x,   W_uk_rope, b_uk_rope, kr,  MROWS, 768,  DM_);
    // rope + head scatter
    rope_concat_kernel<<<(MROWS * 384 + 255) / 256, 256>>>(qn, qr, kn, kr, vv, q, k, vh);
    // causal flash attention
    attn_kernel<<<dim3(S_ / 64, B_ * H_), t, ATT_SMEM>>>(q, k, vh, o);
    // output projection
    sgemm_bias<<<dim3(6, 64), t>>>(o, W_o, b_o, out, MROWS, DM_, 1536);
}

// round 2
// speedup vs baseline: 2.4258x; 2.4258x over previous
#include <cuda_runtime.h>
#include <math_constants.h>
#include <math.h>
#include <stdint.h>

#define B_   4
#define S_   2048
#define H_   12
#define DM_  768
#define MROWS (B_*S_)   // 8192

// ---------------- scratch ----------------
__device__ float g_Cq [MROWS*128];
__device__ float g_Ckv[MROWS*128];
__device__ float g_qn [MROWS*768];
__device__ float g_kn [MROWS*768];
__device__ float g_qr [MROWS*768];
__device__ float g_kr [MROWS*768];
__device__ float g_v  [MROWS*1536];
__device__ float g_q  [(size_t)B_*H_*S_*128];
__device__ float g_k  [(size_t)B_*H_*S_*128];
__device__ float g_vh [(size_t)B_*H_*S_*128];
__device__ float g_o  [MROWS*1536];

// ---------------- helpers ----------------
__device__ __forceinline__ float f2tf(float x) {
    asm("cvt.rna.tf32.f32 %0, %0;" : "+f"(x));
    return x;
}
__device__ __forceinline__ void mma8(float* d, const uint32_t* a, const uint32_t* b) {
    asm volatile(
        "mma.sync.aligned.m16n8k8.row.col.f32.tf32.tf32.f32 "
        "{%0,%1,%2,%3},{%4,%5,%6,%7},{%8,%9},{%0,%1,%2,%3};"
        : "+f"(d[0]), "+f"(d[1]), "+f"(d[2]), "+f"(d[3])
        : "r"(a[0]), "r"(a[1]), "r"(a[2]), "r"(a[3]), "r"(b[0]), "r"(b[1]));
}

// ---------------- fp32 SGEMM (kept for tiny latent projections) ----------------
#define GBM 128
#define GBN 128
#define GBK 16

__global__ __launch_bounds__(256)
void sgemm_bias(const float* __restrict__ X, const float* __restrict__ W,
                const float* __restrict__ bias, float* __restrict__ Y,
                int M, int N, int K)
{
    __shared__ float As[GBK][GBM + 4];
    __shared__ float Bs[GBK][GBN + 4];

    const int tid = threadIdx.x;
    const int tx = tid & 15;
    const int ty = tid >> 4;
    const int row0 = blockIdx.y * GBM;
    const int col0 = blockIdx.x * GBN;

    float acc[8][8];
#pragma unroll
    for (int i = 0; i < 8; i++)
#pragma unroll
        for (int j = 0; j < 8; j++) acc[i][j] = 0.f;

    for (int k0 = 0; k0 < K; k0 += GBK) {
#pragma unroll
        for (int it = 0; it < 2; it++) {
            int idx = tid + it * 256;
            int r = idx >> 2;
            int c4 = (idx & 3) << 2;
            float4 va = *(const float4*)&X[(size_t)(row0 + r) * K + k0 + c4];
            As[c4 + 0][r] = va.x; As[c4 + 1][r] = va.y;
            As[c4 + 2][r] = va.z; As[c4 + 3][r] = va.w;
            float4 vb = *(const float4*)&W[(size_t)(col0 + r) * K + k0 + c4];
            Bs[c4 + 0][r] = vb.x; Bs[c4 + 1][r] = vb.y;
            Bs[c4 + 2][r] = vb.z; Bs[c4 + 3][r] = vb.w;
        }
        __syncthreads();

#pragma unroll
        for (int kk = 0; kk < GBK; kk++) {
            float a[8], b[8];
            float4 a0 = *(const float4*)&As[kk][ty * 8];
            float4 a1 = *(const float4*)&As[kk][ty * 8 + 4];
            a[0]=a0.x; a[1]=a0.y; a[2]=a0.z; a[3]=a0.w;
            a[4]=a1.x; a[5]=a1.y; a[6]=a1.z; a[7]=a1.w;
            float4 b0 = *(const float4*)&Bs[kk][tx * 8];
            float4 b1 = *(const float4*)&Bs[kk][tx * 8 + 4];
            b[0]=b0.x; b[1]=b0.y; b[2]=b0.z; b[3]=b0.w;
            b[4]=b1.x; b[5]=b1.y; b[6]=b1.z; b[7]=b1.w;
#pragma unroll
            for (int i = 0; i < 8; i++)
#pragma unroll
                for (int j = 0; j < 8; j++)
                    acc[i][j] = fmaf(a[i], b[j], acc[i][j]);
        }
        __syncthreads();
    }

#pragma unroll
    for (int i = 0; i < 8; i++) {
        int m = row0 + ty * 8 + i;
#pragma unroll
        for (int j = 0; j < 8; j += 4) {
            int n = col0 + tx * 8 + j;
            float4 o;
            o.x = acc[i][j + 0] + bias[n + 0];
            o.y = acc[i][j + 1] + bias[n + 1];
            o.z = acc[i][j + 2] + bias[n + 2];
            o.w = acc[i][j + 3] + bias[n + 3];
            *(float4*)&Y[(size_t)m * N + n] = o;
        }
    }
}

// ---------------- TF32 tensor-core SGEMM: Y[M,N] = X[M,K] @ W[N,K]^T + bias ----------------
#define TBM 128
#define TBN 128
#define TBK 32
#define TST 36   // smem stride (== 4 mod 32 -> conflict-free fragment loads)

__global__ __launch_bounds__(256)
void sgemm_tf32(const float* __restrict__ X, const float* __restrict__ W,
                const float* __restrict__ bias, float* __restrict__ Y,
                int M, int N, int K)
{
    __shared__ float As[TBM * TST];
    __shared__ float Bs[TBN * TST];

    const int tid  = threadIdx.x;
    const int lane = tid & 31;
    const int wid  = tid >> 5;
    const int g    = lane >> 2;   // groupID
    const int t    = lane & 3;    // thread-in-group
    const int wm   = wid & 3;     // warp row 0..3 (32 rows each)
    const int wn   = wid >> 2;    // warp col 0..1 (64 cols each)
    const int row0 = blockIdx.y * TBM;
    const int col0 = blockIdx.x * TBN;

    float c[2][8][4];
#pragma unroll
    for (int mt = 0; mt < 2; mt++)
#pragma unroll
        for (int nt = 0; nt < 8; nt++)
#pragma unroll
            for (int j = 0; j < 4; j++) c[mt][nt][j] = 0.f;

    float4 pa[4], pb[4];
#pragma unroll
    for (int i = 0; i < 4; i++) {
        int idx = tid + i * 256;
        int r = idx >> 3, cc = (idx & 7) << 2;
        pa[i] = *(const float4*)&X[(size_t)(row0 + r) * K + cc];
        pb[i] = *(const float4*)&W[(size_t)(col0 + r) * K + cc];
    }

    for (int k0 = 0; k0 < K; k0 += TBK) {
        // store prefetched tile (rounded to tf32)
#pragma unroll
        for (int i = 0; i < 4; i++) {
            int idx = tid + i * 256;
            int r = idx >> 3, cc = (idx & 7) << 2;
            float* a = &As[r * TST + cc];
            a[0] = f2tf(pa[i].x); a[1] = f2tf(pa[i].y);
            a[2] = f2tf(pa[i].z); a[3] = f2tf(pa[i].w);
            float* bsm = &Bs[r * TST + cc];
            bsm[0] = f2tf(pb[i].x); bsm[1] = f2tf(pb[i].y);
            bsm[2] = f2tf(pb[i].z); bsm[3] = f2tf(pb[i].w);
        }
        __syncthreads();

        if (k0 + TBK < K) {
#pragma unroll
            for (int i = 0; i < 4; i++) {
                int idx = tid + i * 256;
                int r = idx >> 3, cc = (idx & 7) << 2;
                pa[i] = *(const float4*)&X[(size_t)(row0 + r) * K + k0 + TBK + cc];
                pb[i] = *(const float4*)&W[(size_t)(col0 + r) * K + k0 + TBK + cc];
            }
        }

#pragma unroll
        for (int kk = 0; kk < 4; kk++) {
            uint32_t af[2][4];
#pragma unroll
            for (int mt = 0; mt < 2; mt++) {
                int rb = wm * 32 + mt * 16;
                af[mt][0] = __float_as_uint(As[(rb + g)     * TST + kk * 8 + t]);
                af[mt][1] = __float_as_uint(As[(rb + g + 8) * TST + kk * 8 + t]);
                af[mt][2] = __float_as_uint(As[(rb + g)     * TST + kk * 8 + t + 4]);
                af[mt][3] = __float_as_uint(As[(rb + g + 8) * TST + kk * 8 + t + 4]);
            }
            uint32_t bf[8][2];
#pragma unroll
            for (int nt = 0; nt < 8; nt++) {
                int nb = wn * 64 + nt * 8;
                bf[nt][0] = __float_as_uint(Bs[(nb + g) * TST + kk * 8 + t]);
                bf[nt][1] = __float_as_uint(Bs[(nb + g) * TST + kk * 8 + t + 4]);
            }
#pragma unroll
            for (int mt = 0; mt < 2; mt++)
#pragma unroll
                for (int nt = 0; nt < 8; nt++)
                    mma8(c[mt][nt], af[mt], bf[nt]);
        }
        __syncthreads();
    }

    // epilogue
#pragma unroll
    for (int mt = 0; mt < 2; mt++) {
        int r0 = row0 + wm * 32 + mt * 16 + g;
#pragma unroll
        for (int nt = 0; nt < 8; nt++) {
            int n = col0 + wn * 64 + nt * 8 + 2 * t;
            float b0 = bias[n], b1 = bias[n + 1];
            float2 v0 = make_float2(c[mt][nt][0] + b0, c[mt][nt][1] + b1);
            float2 v1 = make_float2(c[mt][nt][2] + b0, c[mt][nt][3] + b1);
            *(float2*)&Y[(size_t)r0 * N + n]       = v0;
            *(float2*)&Y[(size_t)(r0 + 8) * N + n] = v1;
        }
    }
}

// ---------------- rope + flat-concat head scatter (unchanged, proven) ----------------
__global__ void rope_concat_kernel(const float* __restrict__ qn, const float* __restrict__ qr,
                                   const float* __restrict__ kn, const float* __restrict__ kr,
                                   const float* __restrict__ vv,
                                   float* __restrict__ q, float* __restrict__ k,
                                   float* __restrict__ vh)
{
    int tIdx = blockIdx.x * blockDim.x + threadIdx.x;
    if (tIdx >= MROWS * 384) return;
    int i  = tIdx % 384;
    int bs = tIdx / 384;
    int s  = bs % S_;
    int b  = bs / S_;

    float inv = (float)exp(-((double)(2 * i) / 768.0) * log(10000.0));
    float ang = (float)s * inv;
    float c = cosf(ang), sn = sinf(ang);

    int f  = 2 * i;
    int f2 = 768 + 2 * i;
    int h  = f  >> 7, d  = f  & 127;
    int h2 = f2 >> 7, d2 = f2 & 127;
    size_t dstN = (((size_t)(b * H_ + h )) * S_ + s) * 128 + d;
    size_t dstR = (((size_t)(b * H_ + h2)) * S_ + s) * 128 + d2;

    {
        const float* nsrc = qn + (size_t)bs * 768;
        const float* rsrc = qr + (size_t)bs * 768;
        float e = rsrc[f], o = rsrc[f + 1];
        q[dstN] = nsrc[f];     q[dstN + 1] = nsrc[f + 1];
        q[dstR] = e * c - o * sn;  q[dstR + 1] = e * sn + o * c;
    }
    {
        const float* nsrc = kn + (size_t)bs * 768;
        const float* rsrc = kr + (size_t)bs * 768;
        float e = rsrc[f], o = rsrc[f + 1];
        k[dstN] = nsrc[f];     k[dstN + 1] = nsrc[f + 1];
        k[dstR] = e * c - o * sn;  k[dstR + 1] = e * sn + o * c;
    }
    {
        const float* src = vv + (size_t)bs * 1536 + 4 * i;
#pragma unroll
        for (int u = 0; u < 4; u++) {
            int fv = 4 * i + u;
            int hv = fv >> 7, dv = fv & 127;
            vh[(((size_t)(b * H_ + hv)) * S_ + s) * 128 + dv] = src[u];
        }
    }
}

// ---------------- TF32 flash attention: 128 queries x 64 keys per tile ----------------
#define AST 132   // K/V smem row stride
#define PST 68    // P smem row stride
#define ATT_SMEM_BYTES ((2*64*AST + 128*PST) * 4)   // 102400

__global__ __launch_bounds__(256, 1)
void attn_tf32(const float* __restrict__ q, const float* __restrict__ k,
               const float* __restrict__ v, float* __restrict__ o)
{
    extern __shared__ float sm[];
    float* Ks = sm;                    // [64][AST]
    float* Vs = sm + 64 * AST;         // [64][AST]
    float* Ps = sm + 2 * 64 * AST;     // [128][PST]
    float* Qs = sm;                    // overlay (128*AST floats, fits in Ks+Vs)

    const int tid  = threadIdx.x;
    const int lane = tid & 31;
    const int wid  = tid >> 5;         // 8 warps, each owns 16 query rows
    const int g    = lane >> 2;
    const int t    = lane & 3;
    const int qt   = (S_ / 128 - 1) - blockIdx.x;   // big tiles first
    const int bh   = blockIdx.y;
    const int b    = bh / H_, h = bh % H_;
    const size_t base = (size_t)bh * S_ * 128;
    const float scale = 0.08838834764831845f;       // 1/sqrt(128)

    // ---- stage Q (scaled, tf32-rounded) and pull fragments to registers ----
#pragma unroll
    for (int i = 0; i < 16; i++) {
        int idx = tid + i * 256;
        int r = idx >> 5, c4 = (idx & 31) << 2;
        float4 qv = *(const float4*)&q[base + (size_t)(qt * 128 + r) * 128 + c4];
        float* dst = &Qs[r * AST + c4];
        dst[0] = f2tf(qv.x * scale); dst[1] = f2tf(qv.y * scale);
        dst[2] = f2tf(qv.z * scale); dst[3] = f2tf(qv.w * scale);
    }
    __syncthreads();

    const int wr = wid * 16;
    uint32_t qf[16][4];
#pragma unroll
    for (int kk = 0; kk < 16; kk++) {
        qf[kk][0] = __float_as_uint(Qs[(wr + g)     * AST + kk * 8 + t]);
        qf[kk][1] = __float_as_uint(Qs[(wr + g + 8) * AST + kk * 8 + t]);
        qf[kk][2] = __float_as_uint(Qs[(wr + g)     * AST + kk * 8 + t + 4]);
        qf[kk][3] = __float_as_uint(Qs[(wr + g + 8) * AST + kk * 8 + t + 4]);
    }
    __syncthreads();

    float of[16][4];
#pragma unroll
    for (int nt = 0; nt < 16; nt++)
#pragma unroll
        for (int j = 0; j < 4; j++) of[nt][j] = 0.f;
    float m0 = -CUDART_INF_F, m1 = -CUDART_INF_F, l0 = 0.f, l1 = 0.f;

    const int row0g = qt * 128 + wr + g;
    const int row1g = row0g + 8;
    const int nkt = 2 * qt + 2;

    for (int kt = 0; kt < nkt; kt++) {
        // load K and V tiles (tf32-rounded)
#pragma unroll
        for (int i = 0; i < 8; i++) {
            int idx = tid + i * 256;
            int r = idx >> 5, c4 = (idx & 31) << 2;
            size_t goff = base + (size_t)(kt * 64 + r) * 128 + c4;
            float4 kv = *(const float4*)&k[goff];
            float* kd = &Ks[r * AST + c4];
            kd[0] = f2tf(kv.x); kd[1] = f2tf(kv.y); kd[2] = f2tf(kv.z); kd[3] = f2tf(kv.w);
            float4 vv4 = *(const float4*)&v[goff];
            float* vd = &Vs[r * AST + c4];
            vd[0] = f2tf(vv4.x); vd[1] = f2tf(vv4.y); vd[2] = f2tf(vv4.z); vd[3] = f2tf(vv4.w);
        }
        __syncthreads();

        // ---- S = Q @ K^T ----
        float sc[8][4];
#pragma unroll
        for (int nt = 0; nt < 8; nt++)
#pragma unroll
            for (int j = 0; j < 4; j++) sc[nt][j] = 0.f;

#pragma unroll
        for (int kk = 0; kk < 16; kk++) {
#pragma unroll
            for (int nt = 0; nt < 8; nt++) {
                uint32_t bf[2];
                bf[0] = __float_as_uint(Ks[(nt * 8 + g) * AST + kk * 8 + t]);
                bf[1] = __float_as_uint(Ks[(nt * 8 + g) * AST + kk * 8 + t + 4]);
                mma8(sc[nt], qf[kk], bf);
            }
        }

        // ---- causal mask (only last two key tiles can intersect diagonal) ----
        if (kt >= 2 * qt) {
            int cbase = kt * 64 + 2 * t;
#pragma unroll
            for (int nt = 0; nt < 8; nt++) {
                int col = cbase + nt * 8;
                if (col     > row0g) sc[nt][0] = -CUDART_INF_F;
                if (col + 1 > row0g) sc[nt][1] = -CUDART_INF_F;
                if (col     > row1g) sc[nt][2] = -CUDART_INF_F;
                if (col + 1 > row1g) sc[nt][3] = -CUDART_INF_F;
            }
        }

        // ---- online softmax ----
        float rmax0 = -CUDART_INF_F, rmax1 = -CUDART_INF_F;
#pragma unroll
        for (int nt = 0; nt < 8; nt++) {
            rmax0 = fmaxf(rmax0, fmaxf(sc[nt][0], sc[nt][1]));
            rmax1 = fmaxf(rmax1, fmaxf(sc[nt][2], sc[nt][3]));
        }
        rmax0 = fmaxf(rmax0, __shfl_xor_sync(0xffffffffu, rmax0, 1, 4));
        rmax0 = fmaxf(rmax0, __shfl_xor_sync(0xffffffffu, rmax0, 2, 4));
        rmax1 = fmaxf(rmax1, __shfl_xor_sync(0xffffffffu, rmax1, 1, 4));
        rmax1 = fmaxf(rmax1, __shfl_xor_sync(0xffffffffu, rmax1, 2, 4));

        float mn0 = fmaxf(m0, rmax0);
        float mn1 = fmaxf(m1, rmax1);
        float fac0 = __expf(m0 - mn0);
        float fac1 = __expf(m1 - mn1);
        m0 = mn0; m1 = mn1;

        float rs0 = 0.f, rs1 = 0.f;
#pragma unroll
        for (int nt = 0; nt < 8; nt++) {
            float p0 = __expf(sc[nt][0] - mn0);
            float p1 = __expf(sc[nt][1] - mn0);
            float p2 = __expf(sc[nt][2] - mn1);
            float p3 = __expf(sc[nt][3] - mn1);
            sc[nt][0] = p0; sc[nt][1] = p1; sc[nt][2] = p2; sc[nt][3] = p3;
            rs0 += p0 + p1; rs1 += p2 + p3;
        }
        rs0 += __shfl_xor_sync(0xffffffffu, rs0, 1, 4);
        rs0 += __shfl_xor_sync(0xffffffffu, rs0, 2, 4);
        rs1 += __shfl_xor_sync(0xffffffffu, rs1, 1, 4);
        rs1 += __shfl_xor_sync(0xffffffffu, rs1, 2, 4);
        l0 = l0 * fac0 + rs0;
        l1 = l1 * fac1 + rs1;

#pragma unroll
        for (int nt = 0; nt < 16; nt++) {
            of[nt][0] *= fac0; of[nt][1] *= fac0;
            of[nt][2] *= fac1; of[nt][3] *= fac1;
        }

        // store P fragments (tf32-rounded); rows are warp-private
#pragma unroll
        for (int nt = 0; nt < 8; nt++) {
            int col = nt * 8 + 2 * t;
            Ps[(wr + g)     * PST + col]     = f2tf(sc[nt][0]);
            Ps[(wr + g)     * PST + col + 1] = f2tf(sc[nt][1]);
            Ps[(wr + g + 8) * PST + col]     = f2tf(sc[nt][2]);
            Ps[(wr + g + 8) * PST + col + 1] = f2tf(sc[nt][3]);
        }
        __syncwarp();

        // ---- O += P @ V ----
#pragma unroll
        for (int kk = 0; kk < 8; kk++) {
            uint32_t ap[4];
            ap[0] = __float_as_uint(Ps[(wr + g)     * PST + kk * 8 + t]);
            ap[1] = __float_as_uint(Ps[(wr + g + 8) * PST + kk * 8 + t]);
            ap[2] = __float_as_uint(Ps[(wr + g)     * PST + kk * 8 + t + 4]);
            ap[3] = __float_as_uint(Ps[(wr + g + 8) * PST + kk * 8 + t + 4]);
#pragma unroll
            for (int nt = 0; nt < 16; nt++) {
                uint32_t bf[2];
                bf[0] = __float_as_uint(Vs[(kk * 8 + t)     * AST + nt * 8 + g]);
                bf[1] = __float_as_uint(Vs[(kk * 8 + t + 4) * AST + nt * 8 + g]);
                mma8(of[nt], ap, bf);
            }
        }
        __syncthreads();
    }

    // ---- epilogue: normalize, write to [B,S,H*128] ----
    float inv0 = 1.0f / l0;
    float inv1 = 1.0f / l1;
    size_t orow0 = ((size_t)(b * S_ + row0g)) * 1536 + h * 128;
    size_t orow1 = ((size_t)(b * S_ + row1g)) * 1536 + h * 128;
#pragma unroll
    for (int nt = 0; nt < 16; nt++) {
        int col = nt * 8 + 2 * t;
        *(float2*)&o[orow0 + col] = make_float2(of[nt][0] * inv0, of[nt][1] * inv0);
        *(float2*)&o[orow1 + col] = make_float2(of[nt][2] * inv1, of[nt][3] * inv1);
    }
}

// ---------------- launch ----------------
extern "C" void kernel_launch(void* const* d_in, const int* in_sizes, int n_in,
                              void* d_out, int out_size)
{
    const float* x         = (const float*)d_in[0];
    const float* W_dkv     = (const float*)d_in[2];
    const float* b_dkv     = (const float*)d_in[3];
    const float* W_dq      = (const float*)d_in[4];
    const float* b_dq      = (const float*)d_in[5];
    const float* W_uk_nope = (const float*)d_in[6];
    const float* b_uk_nope = (const float*)d_in[7];
    const float* W_uv      = (const float*)d_in[8];
    const float* b_uv      = (const float*)d_in[9];
    const float* W_uq_nope = (const float*)d_in[10];
    const float* b_uq_nope = (const float*)d_in[11];
    const float* W_uq_rope = (const float*)d_in[12];
    const float* b_uq_rope = (const float*)d_in[13];
    const float* W_uk_rope = (const float*)d_in[14];
    const float* b_uk_rope = (const float*)d_in[15];
    const float* W_o       = (const float*)d_in[16];
    const float* b_o       = (const float*)d_in[17];
    float* out = (float*)d_out;

    float *Cq, *Ckv, *qn, *kn, *qr, *kr, *vv, *q, *k, *vh, *o;
    cudaGetSymbolAddress((void**)&Cq,  g_Cq);
    cudaGetSymbolAddress((void**)&Ckv, g_Ckv);
    cudaGetSymbolAddress((void**)&qn,  g_qn);
    cudaGetSymbolAddress((void**)&kn,  g_kn);
    cudaGetSymbolAddress((void**)&qr,  g_qr);
    cudaGetSymbolAddress((void**)&kr,  g_kr);
    cudaGetSymbolAddress((void**)&vv,  g_v);
    cudaGetSymbolAddress((void**)&q,   g_q);
    cudaGetSymbolAddress((void**)&k,   g_k);
    cudaGetSymbolAddress((void**)&vh,  g_vh);
    cudaGetSymbolAddress((void**)&o,   g_o);

    cudaFuncSetAttribute(attn_tf32, cudaFuncAttributeMaxDynamicSharedMemorySize, ATT_SMEM_BYTES);

    dim3 t(256);
    // latent projections in fp32 (accuracy anchor; tiny)
    sgemm_bias<<<dim3(1, 64), t>>>(x,   W_dq,      b_dq,      Cq,  MROWS, 128,  DM_);
    sgemm_bias<<<dim3(1, 64), t>>>(x,   W_dkv,     b_dkv,     Ckv, MROWS, 128,  DM_);
    // up projections in tf32
    sgemm_tf32<<<dim3(6, 64), t>>>(Cq,  W_uq_nope, b_uq_nope, qn,  MROWS, 768,  128);
    sgemm_tf32<<<dim3(6, 64), t>>>(Ckv, W_uk_nope, b_uk_nope, kn,  MROWS, 768,  128);
    sgemm_tf32<<<dim3(6, 64), t>>>(Cq,  W_uq_rope, b_uq_rope, qr,  MROWS, 768,  128);
    sgemm_tf32<<<dim3(12,64), t>>>(Ckv, W_uv,      b_uv,      vv,  MROWS, 1536, 128);
    sgemm_tf32<<<dim3(6, 64), t>>>(x,   W_uk_rope, b_uk_rope, kr,  MROWS, 768,  DM_);
    // rope + head scatter
    rope_concat_kernel<<<(MROWS * 384 + 255) / 256, 256>>>(qn, qr, kn, kr, vv, q, k, vh);
    // tf32 flash attention
    attn_tf32<<<dim3(S_ / 128, B_ * H_), t, ATT_SMEM_BYTES>>>(q, k, vh, o);
    // output projection in tf32
    sgemm_tf32<<<dim3(6, 64), t>>>(o, W_o, b_o, out, MROWS, DM_, 1536);
}

// round 3
// speedup vs baseline: 3.3345x; 1.3746x over previous
#include <cuda_runtime.h>
#include <math_constants.h>
#include <math.h>
#include <stdint.h>

#define B_   4
#define S_   2048
#define H_   12
#define DM_  768
#define MROWS (B_*S_)   // 8192

// ---------------- scratch ----------------
__device__ float g_Cq [MROWS*128];
__device__ float g_Ckv[MROWS*128];
__device__ float g_qn [MROWS*768];
__device__ float g_kn [MROWS*768];
__device__ float g_qr [MROWS*768];
__device__ float g_kr [MROWS*768];
__device__ float g_v  [MROWS*1536];
__device__ float g_q  [(size_t)B_*H_*S_*128];
__device__ float g_k  [(size_t)B_*H_*S_*128];
__device__ float g_vh [(size_t)B_*H_*S_*128];
__device__ float g_o  [MROWS*1536];
__device__ float g_freq[384];

// ---------------- helpers ----------------
__device__ __forceinline__ float f2tf(float x) {
    asm("cvt.rna.tf32.f32 %0, %0;" : "+f"(x));
    return x;
}
__device__ __forceinline__ void mma8(float* d, const uint32_t* a, const uint32_t* b) {
    asm volatile(
        "mma.sync.aligned.m16n8k8.row.col.f32.tf32.tf32.f32 "
        "{%0,%1,%2,%3},{%4,%5,%6,%7},{%8,%9},{%0,%1,%2,%3};"
        : "+f"(d[0]), "+f"(d[1]), "+f"(d[2]), "+f"(d[3])
        : "r"(a[0]), "r"(a[1]), "r"(a[2]), "r"(a[3]), "r"(b[0]), "r"(b[1]));
}
__device__ __forceinline__ uint32_t smem_u32(const void* p) {
    return (uint32_t)__cvta_generic_to_shared(p);
}
__device__ __forceinline__ void cpasync16(uint32_t dst, const float* src) {
    asm volatile("cp.async.cg.shared.global [%0], [%1], 16;" :: "r"(dst), "l"(src));
}
// swizzled smem read for 128-float-wide tiles: chunk(16B) index ^= (row & 7)
__device__ __forceinline__ float ldsw(const float* base, int r, int c) {
    return base[((r << 7) + c) ^ ((r & 7) << 2)];
}

// ---------------- freq table ----------------
__global__ void init_freq_kernel() {
    int i = threadIdx.x + blockIdx.x * blockDim.x;
    if (i < 384)
        g_freq[i] = (float)exp(-((double)(2 * i) / 768.0) * log(10000.0));
}

// ---------------- fp32 dual SGEMM for the two latent projections ----------------
// Y1 = X @ W1^T + b1 (N=128), Y2 = X @ W2^T + b2 (N=128). blockIdx.x picks which.
#define GBM 128
#define GBK 16

__global__ __launch_bounds__(256)
void sgemm_bias_dual(const float* __restrict__ X,
                     const float* __restrict__ W1, const float* __restrict__ bias1, float* __restrict__ Y1,
                     const float* __restrict__ W2, const float* __restrict__ bias2, float* __restrict__ Y2,
                     int M, int K)
{
    const int N = 128;
    const float* W    = blockIdx.x ? W2 : W1;
    const float* bias = blockIdx.x ? bias2 : bias1;
    float*       Y    = blockIdx.x ? Y2 : Y1;

    __shared__ float As[GBK][GBM + 4];
    __shared__ float Bs[GBK][128 + 4];

    const int tid = threadIdx.x;
    const int tx = tid & 15;
    const int ty = tid >> 4;
    const int row0 = blockIdx.y * GBM;

    float acc[8][8];
#pragma unroll
    for (int i = 0; i < 8; i++)
#pragma unroll
        for (int j = 0; j < 8; j++) acc[i][j] = 0.f;

    for (int k0 = 0; k0 < K; k0 += GBK) {
#pragma unroll
        for (int it = 0; it < 2; it++) {
            int idx = tid + it * 256;
            int r = idx >> 2;
            int c4 = (idx & 3) << 2;
            float4 va = *(const float4*)&X[(size_t)(row0 + r) * K + k0 + c4];
            As[c4 + 0][r] = va.x; As[c4 + 1][r] = va.y;
            As[c4 + 2][r] = va.z; As[c4 + 3][r] = va.w;
            float4 vb = *(const float4*)&W[(size_t)r * K + k0 + c4];
            Bs[c4 + 0][r] = vb.x; Bs[c4 + 1][r] = vb.y;
            Bs[c4 + 2][r] = vb.z; Bs[c4 + 3][r] = vb.w;
        }
        __syncthreads();

#pragma unroll
        for (int kk = 0; kk < GBK; kk++) {
            float a[8], b[8];
            float4 a0 = *(const float4*)&As[kk][ty * 8];
            float4 a1 = *(const float4*)&As[kk][ty * 8 + 4];
            a[0]=a0.x; a[1]=a0.y; a[2]=a0.z; a[3]=a0.w;
            a[4]=a1.x; a[5]=a1.y; a[6]=a1.z; a[7]=a1.w;
            float4 b0 = *(const float4*)&Bs[kk][tx * 8];
            float4 b1 = *(const float4*)&Bs[kk][tx * 8 + 4];
            b[0]=b0.x; b[1]=b0.y; b[2]=b0.z; b[3]=b0.w;
            b[4]=b1.x; b[5]=b1.y; b[6]=b1.z; b[7]=b1.w;
#pragma unroll
            for (int i = 0; i < 8; i++)
#pragma unroll
                for (int j = 0; j < 8; j++)
                    acc[i][j] = fmaf(a[i], b[j], acc[i][j]);
        }
        __syncthreads();
    }

#pragma unroll
    for (int i = 0; i < 8; i++) {
        int m = row0 + ty * 8 + i;
#pragma unroll
        for (int j = 0; j < 8; j += 4) {
            int n = tx * 8 + j;
            float4 o;
            o.x = acc[i][j + 0] + bias[n + 0];
            o.y = acc[i][j + 1] + bias[n + 1];
            o.z = acc[i][j + 2] + bias[n + 2];
            o.w = acc[i][j + 3] + bias[n + 3];
            *(float4*)&Y[(size_t)m * N + n] = o;
        }
    }
}

// ---------------- TF32 tensor-core SGEMM ----------------
#define TBM 128
#define TBN 128
#define TBK 32
#define TST 36

__global__ __launch_bounds__(256)
void sgemm_tf32(const float* __restrict__ X, const float* __restrict__ W,
                const float* __restrict__ bias, float* __restrict__ Y,
                int M, int N, int K)
{
    __shared__ float As[TBM * TST];
    __shared__ float Bs[TBN * TST];

    const int tid  = threadIdx.x;
    const int lane = tid & 31;
    const int wid  = tid >> 5;
    const int g    = lane >> 2;
    const int t    = lane & 3;
    const int wm   = wid & 3;
    const int wn   = wid >> 2;
    const int row0 = blockIdx.y * TBM;
    const int col0 = blockIdx.x * TBN;

    float c[2][8][4];
#pragma unroll
    for (int mt = 0; mt < 2; mt++)
#pragma unroll
        for (int nt = 0; nt < 8; nt++)
#pragma unroll
            for (int j = 0; j < 4; j++) c[mt][nt][j] = 0.f;

    float4 pa[4], pb[4];
#pragma unroll
    for (int i = 0; i < 4; i++) {
        int idx = tid + i * 256;
        int r = idx >> 3, cc = (idx & 7) << 2;
        pa[i] = *(const float4*)&X[(size_t)(row0 + r) * K + cc];
        pb[i] = *(const float4*)&W[(size_t)(col0 + r) * K + cc];
    }

    for (int k0 = 0; k0 < K; k0 += TBK) {
#pragma unroll
        for (int i = 0; i < 4; i++) {
            int idx = tid + i * 256;
            int r = idx >> 3, cc = (idx & 7) << 2;
            float* a = &As[r * TST + cc];
            a[0] = f2tf(pa[i].x); a[1] = f2tf(pa[i].y);
            a[2] = f2tf(pa[i].z); a[3] = f2tf(pa[i].w);
            float* bsm = &Bs[r * TST + cc];
            bsm[0] = f2tf(pb[i].x); bsm[1] = f2tf(pb[i].y);
            bsm[2] = f2tf(pb[i].z); bsm[3] = f2tf(pb[i].w);
        }
        __syncthreads();

        if (k0 + TBK < K) {
#pragma unroll
            for (int i = 0; i < 4; i++) {
                int idx = tid + i * 256;
                int r = idx >> 3, cc = (idx & 7) << 2;
                pa[i] = *(const float4*)&X[(size_t)(row0 + r) * K + k0 + TBK + cc];
                pb[i] = *(const float4*)&W[(size_t)(col0 + r) * K + k0 + TBK + cc];
            }
        }

#pragma unroll
        for (int kk = 0; kk < 4; kk++) {
            uint32_t af[2][4];
#pragma unroll
            for (int mt = 0; mt < 2; mt++) {
                int rb = wm * 32 + mt * 16;
                af[mt][0] = __float_as_uint(As[(rb + g)     * TST + kk * 8 + t]);
                af[mt][1] = __float_as_uint(As[(rb + g + 8) * TST + kk * 8 + t]);
                af[mt][2] = __float_as_uint(As[(rb + g)     * TST + kk * 8 + t + 4]);
                af[mt][3] = __float_as_uint(As[(rb + g + 8) * TST + kk * 8 + t + 4]);
            }
            uint32_t bf[8][2];
#pragma unroll
            for (int nt = 0; nt < 8; nt++) {
                int nb = wn * 64 + nt * 8;
                bf[nt][0] = __float_as_uint(Bs[(nb + g) * TST + kk * 8 + t]);
                bf[nt][1] = __float_as_uint(Bs[(nb + g) * TST + kk * 8 + t + 4]);
            }
#pragma unroll
            for (int mt = 0; mt < 2; mt++)
#pragma unroll
                for (int nt = 0; nt < 8; nt++)
                    mma8(c[mt][nt], af[mt], bf[nt]);
        }
        __syncthreads();
    }

#pragma unroll
    for (int mt = 0; mt < 2; mt++) {
        int r0 = row0 + wm * 32 + mt * 16 + g;
#pragma unroll
        for (int nt = 0; nt < 8; nt++) {
            int n = col0 + wn * 64 + nt * 8 + 2 * t;
            float b0 = bias[n], b1 = bias[n + 1];
            float2 v0 = make_float2(c[mt][nt][0] + b0, c[mt][nt][1] + b1);
            float2 v1 = make_float2(c[mt][nt][2] + b0, c[mt][nt][3] + b1);
            *(float2*)&Y[(size_t)r0 * N + n]       = v0;
            *(float2*)&Y[(size_t)(r0 + 8) * N + n] = v1;
        }
    }
}

// ---------------- rope + head scatter; writes tf32-rounded q (pre-scaled), k, v ----------------
__global__ void rope_concat_kernel(const float* __restrict__ qn, const float* __restrict__ qr,
                                   const float* __restrict__ kn, const float* __restrict__ kr,
                                   const float* __restrict__ vv,
                                   float* __restrict__ q, float* __restrict__ k,
                                   float* __restrict__ vh)
{
    const float scale = 0.08838834764831845f;   // 1/sqrt(128)
    int tIdx = blockIdx.x * blockDim.x + threadIdx.x;
    if (tIdx >= MROWS * 384) return;
    int i  = tIdx % 384;
    int bs = tIdx / 384;
    int s  = bs % S_;
    int b  = bs / S_;

    float inv = g_freq[i];
    float ang = (float)s * inv;
    float c = cosf(ang), sn = sinf(ang);

    int f  = 2 * i;
    int f2 = 768 + 2 * i;
    int h  = f  >> 7, d  = f  & 127;
    int h2 = f2 >> 7, d2 = f2 & 127;
    size_t dstN = (((size_t)(b * H_ + h )) * S_ + s) * 128 + d;
    size_t dstR = (((size_t)(b * H_ + h2)) * S_ + s) * 128 + d2;

    {
        const float* nsrc = qn + (size_t)bs * 768;
        const float* rsrc = qr + (size_t)bs * 768;
        float e = rsrc[f], o = rsrc[f + 1];
        q[dstN]     = f2tf(nsrc[f]     * scale);
        q[dstN + 1] = f2tf(nsrc[f + 1] * scale);
        q[dstR]     = f2tf((e * c - o * sn) * scale);
        q[dstR + 1] = f2tf((e * sn + o * c) * scale);
    }
    {
        const float* nsrc = kn + (size_t)bs * 768;
        const float* rsrc = kr + (size_t)bs * 768;
        float e = rsrc[f], o = rsrc[f + 1];
        k[dstN]     = f2tf(nsrc[f]);
        k[dstN + 1] = f2tf(nsrc[f + 1]);
        k[dstR]     = f2tf(e * c - o * sn);
        k[dstR + 1] = f2tf(e * sn + o * c);
    }
    {
        const float* src = vv + (size_t)bs * 1536 + 4 * i;
#pragma unroll
        for (int u = 0; u < 4; u++) {
            int fv = 4 * i + u;
            int hv = fv >> 7, dv = fv & 127;
            vh[(((size_t)(b * H_ + hv)) * S_ + s) * 128 + dv] = f2tf(src[u]);
        }
    }
}

// ---------------- TF32 flash attention, cp.async double-buffered ----------------
// smem layout (floats): [K0:8192][V0:8192][K1:8192][V1:8192][Ps:128*68]
#define PST 68
#define ATT_SMEM_BYTES ((4*8192 + 128*PST) * 4)   // 165888

__global__ __launch_bounds__(256, 1)
void attn_tf32(const float* __restrict__ q, const float* __restrict__ k,
               const float* __restrict__ v, float* __restrict__ o)
{
    extern __shared__ float sm[];
    float* Ps = sm + 4 * 8192;

    const int tid  = threadIdx.x;
    const int lane = tid & 31;
    const int wid  = tid >> 5;                      // 8 warps x 16 query rows
    const int g    = lane >> 2;
    const int t    = lane & 3;
    const int qt   = (S_ / 128 - 1) - blockIdx.x;   // big tiles first
    const int bh   = blockIdx.y;
    const int b    = bh / H_, h = bh % H_;
    const size_t base = (size_t)bh * S_ * 128;

    // ---- stage Q via cp.async (q is pre-scaled + tf32-rounded) ----
    {
        const float* qg = q + base + (size_t)qt * 128 * 128;
#pragma unroll
        for (int i = 0; i < 16; i++) {
            int ch = tid + i * 256;                 // 16B chunk index, 0..4095
            int r  = ch >> 5;
            int sch = ch ^ (r & 7);
            cpasync16(smem_u32(sm + sch * 4), qg + ch * 4);
        }
        asm volatile("cp.async.commit_group;");
        asm volatile("cp.async.wait_group 0;");
        __syncthreads();
    }

    const int wr = wid * 16;
    uint32_t qf[16][4];
#pragma unroll
    for (int kk = 0; kk < 16; kk++) {
        qf[kk][0] = __float_as_uint(ldsw(sm, wr + g,     kk * 8 + t));
        qf[kk][1] = __float_as_uint(ldsw(sm, wr + g + 8, kk * 8 + t));
        qf[kk][2] = __float_as_uint(ldsw(sm, wr + g,     kk * 8 + t + 4));
        qf[kk][3] = __float_as_uint(ldsw(sm, wr + g + 8, kk * 8 + t + 4));
    }
    __syncthreads();

    float of[16][4];
#pragma unroll
    for (int nt = 0; nt < 16; nt++)
#pragma unroll
        for (int j = 0; j < 4; j++) of[nt][j] = 0.f;
    float m0 = -CUDART_INF_F, m1 = -CUDART_INF_F, l0 = 0.f, l1 = 0.f;

    const int row0g = qt * 128 + wr + g;
    const int row1g = row0g + 8;
    const int nkt = 2 * qt + 2;

    // prologue: tile 0 loads
    {
        const float* kg = k + base;
        const float* vg = v + base;
#pragma unroll
        for (int i = 0; i < 8; i++) {
            int ch = tid + i * 256;                 // 0..2047
            int r  = ch >> 5;
            int sch = ch ^ (r & 7);
            cpasync16(smem_u32(sm + sch * 4),        kg + ch * 4);
            cpasync16(smem_u32(sm + 8192 + sch * 4), vg + ch * 4);
        }
        asm volatile("cp.async.commit_group;");
    }

    for (int kt = 0; kt < nkt; kt++) {
        asm volatile("cp.async.wait_group 0;");
        __syncthreads();            // tile kt ready in buf kt&1; prev compute done everywhere

        if (kt + 1 < nkt) {
            float* dst = sm + ((kt + 1) & 1) * 16384;
            const float* kg = k + base + (size_t)(kt + 1) * 64 * 128;
            const float* vg = v + base + (size_t)(kt + 1) * 64 * 128;
#pragma unroll
            for (int i = 0; i < 8; i++) {
                int ch = tid + i * 256;
                int r  = ch >> 5;
                int sch = ch ^ (r & 7);
                cpasync16(smem_u32(dst + sch * 4),        kg + ch * 4);
                cpasync16(smem_u32(dst + 8192 + sch * 4), vg + ch * 4);
            }
            asm volatile("cp.async.commit_group;");
        }

        const float* Kb = sm + (kt & 1) * 16384;
        const float* Vb = Kb + 8192;

        // ---- S = Q @ K^T ----
        float sc[8][4];
#pragma unroll
        for (int nt = 0; nt < 8; nt++)
#pragma unroll
            for (int j = 0; j < 4; j++) sc[nt][j] = 0.f;

#pragma unroll
        for (int kk = 0; kk < 16; kk++) {
#pragma unroll
            for (int nt = 0; nt < 8; nt++) {
                uint32_t bf[2];
                bf[0] = __float_as_uint(ldsw(Kb, nt * 8 + g, kk * 8 + t));
                bf[1] = __float_as_uint(ldsw(Kb, nt * 8 + g, kk * 8 + t + 4));
                mma8(sc[nt], qf[kk], bf);
            }
        }

        // ---- causal mask ----
        if (kt >= 2 * qt) {
            int cbase = kt * 64 + 2 * t;
#pragma unroll
            for (int nt = 0; nt < 8; nt++) {
                int col = cbase + nt * 8;
                if (col     > row0g) sc[nt][0] = -CUDART_INF_F;
                if (col + 1 > row0g) sc[nt][1] = -CUDART_INF_F;
                if (col     > row1g) sc[nt][2] = -CUDART_INF_F;
                if (col + 1 > row1g) sc[nt][3] = -CUDART_INF_F;
            }
        }

        // ---- online softmax ----
        float rmax0 = -CUDART_INF_F, rmax1 = -CUDART_INF_F;
#pragma unroll
        for (int nt = 0; nt < 8; nt++) {
            rmax0 = fmaxf(rmax0, fmaxf(sc[nt][0], sc[nt][1]));
            rmax1 = fmaxf(rmax1, fmaxf(sc[nt][2], sc[nt][3]));
        }
        rmax0 = fmaxf(rmax0, __shfl_xor_sync(0xffffffffu, rmax0, 1, 4));
        rmax0 = fmaxf(rmax0, __shfl_xor_sync(0xffffffffu, rmax0, 2, 4));
        rmax1 = fmaxf(rmax1, __shfl_xor_sync(0xffffffffu, rmax1, 1, 4));
        rmax1 = fmaxf(rmax1, __shfl_xor_sync(0xffffffffu, rmax1, 2, 4));

        float mn0 = fmaxf(m0, rmax0);
        float mn1 = fmaxf(m1, rmax1);
        float fac0 = __expf(m0 - mn0);
        float fac1 = __expf(m1 - mn1);
        m0 = mn0; m1 = mn1;

        float rs0 = 0.f, rs1 = 0.f;
#pragma unroll
        for (int nt = 0; nt < 8; nt++) {
            float p0 = __expf(sc[nt][0] - mn0);
            float p1 = __expf(sc[nt][1] - mn0);
            float p2 = __expf(sc[nt][2] - mn1);
            float p3 = __expf(sc[nt][3] - mn1);
            sc[nt][0] = p0; sc[nt][1] = p1; sc[nt][2] = p2; sc[nt][3] = p3;
            rs0 += p0 + p1; rs1 += p2 + p3;
        }
        rs0 += __shfl_xor_sync(0xffffffffu, rs0, 1, 4);
        rs0 += __shfl_xor_sync(0xffffffffu, rs0, 2, 4);
        rs1 += __shfl_xor_sync(0xffffffffu, rs1, 1, 4);
        rs1 += __shfl_xor_sync(0xffffffffu, rs1, 2, 4);
        l0 = l0 * fac0 + rs0;
        l1 = l1 * fac1 + rs1;

#pragma unroll
        for (int nt = 0; nt < 16; nt++) {
            of[nt][0] *= fac0; of[nt][1] *= fac0;
            of[nt][2] *= fac1; of[nt][3] *= fac1;
        }

        // P fragments -> smem (warp-private rows)
#pragma unroll
        for (int nt = 0; nt < 8; nt++) {
            int col = nt * 8 + 2 * t;
            *(float2*)&Ps[(wr + g)     * PST + col] = make_float2(f2tf(sc[nt][0]), f2tf(sc[nt][1]));
            *(float2*)&Ps[(wr + g + 8) * PST + col] = make_float2(f2tf(sc[nt][2]), f2tf(sc[nt][3]));
        }
        __syncwarp();

        // ---- O += P @ V ----
#pragma unroll
        for (int kk = 0; kk < 8; kk++) {
            uint32_t ap[4];
            ap[0] = __float_as_uint(Ps[(wr + g)     * PST + kk * 8 + t]);
            ap[1] = __float_as_uint(Ps[(wr + g + 8) * PST + kk * 8 + t]);
            ap[2] = __float_as_uint(Ps[(wr + g)     * PST + kk * 8 + t + 4]);
            ap[3] = __float_as_uint(Ps[(wr + g + 8) * PST + kk * 8 + t + 4]);
#pragma unroll
            for (int nt = 0; nt < 16; nt++) {
                uint32_t bf[2];
                bf[0] = __float_as_uint(ldsw(Vb, kk * 8 + t,     nt * 8 + g));
                bf[1] = __float_as_uint(ldsw(Vb, kk * 8 + t + 4, nt * 8 + g));
                mma8(of[nt], ap, bf);
            }
        }
        __syncthreads();   // all warps done reading buf kt&1 before next iter overwrites sibling
    }

    // ---- epilogue ----
    float inv0 = 1.0f / l0;
    float inv1 = 1.0f / l1;
    size_t orow0 = ((size_t)(b * S_ + row0g)) * 1536 + h * 128;
    size_t orow1 = ((size_t)(b * S_ + row1g)) * 1536 + h * 128;
#pragma unroll
    for (int nt = 0; nt < 16; nt++) {
        int col = nt * 8 + 2 * t;
        *(float2*)&o[orow0 + col] = make_float2(of[nt][0] * inv0, of[nt][1] * inv0);
        *(float2*)&o[orow1 + col] = make_float2(of[nt][2] * inv1, of[nt][3] * inv1);
    }
}

// ---------------- launch ----------------
extern "C" void kernel_launch(void* const* d_in, const int* in_sizes, int n_in,
                              void* d_out, int out_size)
{
    const float* x         = (const float*)d_in[0];
    const float* W_dkv     = (const float*)d_in[2];
    const float* b_dkv     = (const float*)d_in[3];
    const float* W_dq      = (const float*)d_in[4];
    const float* b_dq      = (const float*)d_in[5];
    const float* W_uk_nope = (const float*)d_in[6];
    const float* b_uk_nope = (const float*)d_in[7];
    const float* W_uv      = (const float*)d_in[8];
    const float* b_uv      = (const float*)d_in[9];
    const float* W_uq_nope = (const float*)d_in[10];
    const float* b_uq_nope = (const float*)d_in[11];
    const float* W_uq_rope = (const float*)d_in[12];
    const float* b_uq_rope = (const float*)d_in[13];
    const float* W_uk_rope = (const float*)d_in[14];
    const float* b_uk_rope = (const float*)d_in[15];
    const float* W_o       = (const float*)d_in[16];
    const float* b_o       = (const float*)d_in[17];
    float* out = (float*)d_out;

    float *Cq, *Ckv, *qn, *kn, *qr, *kr, *vv, *q, *k, *vh, *o;
    cudaGetSymbolAddress((void**)&Cq,  g_Cq);
    cudaGetSymbolAddress((void**)&Ckv, g_Ckv);
    cudaGetSymbolAddress((void**)&qn,  g_qn);
    cudaGetSymbolAddress((void**)&kn,  g_kn);
    cudaGetSymbolAddress((void**)&qr,  g_qr);
    cudaGetSymbolAddress((void**)&kr,  g_kr);
    cudaGetSymbolAddress((void**)&vv,  g_v);
    cudaGetSymbolAddress((void**)&q,   g_q);
    cudaGetSymbolAddress((void**)&k,   g_k);
    cudaGetSymbolAddress((void**)&vh,  g_vh);
    cudaGetSymbolAddress((void**)&o,   g_o);

    cudaFuncSetAttribute(attn_tf32, cudaFuncAttributeMaxDynamicSharedMemorySize, ATT_SMEM_BYTES);

    dim3 t(256);
    init_freq_kernel<<<2, 192>>>();
    // latent projections fused (fp32 accuracy anchor)
    sgemm_bias_dual<<<dim3(2, 64), t>>>(x, W_dq, b_dq, Cq, W_dkv, b_dkv, Ckv, MROWS, DM_);
    // up projections in tf32
    sgemm_tf32<<<dim3(6, 64), t>>>(Cq,  W_uq_nope, b_uq_nope, qn,  MROWS, 768,  128);
    sgemm_tf32<<<dim3(6, 64), t>>>(Ckv, W_uk_nope, b_uk_nope, kn,  MROWS, 768,  128);
    sgemm_tf32<<<dim3(6, 64), t>>>(Cq,  W_uq_rope, b_uq_rope, qr,  MROWS, 768,  128);
    sgemm_tf32<<<dim3(12,64), t>>>(Ckv, W_uv,      b_uv,      vv,  MROWS, 1536, 128);
    sgemm_tf32<<<dim3(6, 64), t>>>(x,   W_uk_rope, b_uk_rope, kr,  MROWS, 768,  DM_);
    // rope + head scatter (writes tf32-rounded q/k/v; q pre-scaled)
    rope_concat_kernel<<<(MROWS * 384 + 255) / 256, 256>>>(qn, qr, kn, kr, vv, q, k, vh);
    // tf32 flash attention (pipelined)
    attn_tf32<<<dim3(S_ / 128, B_ * H_), t, ATT_SMEM_BYTES>>>(q, k, vh, o);
    // output projection in tf32
    sgemm_tf32<<<dim3(6, 64), t>>>(o, W_o, b_o, out, MROWS, DM_, 1536);
}

// round 5
// speedup vs baseline: 3.9794x; 1.1934x over previous
#include <cuda_runtime.h>
#include <math_constants.h>
#include <math.h>
#include <stdint.h>

#define B_   4
#define S_   2048
#define H_   12
#define DM_  768
#define MROWS (B_*S_)   // 8192

// ---------------- scratch ----------------
__device__ float g_Cq [MROWS*128];
__device__ float g_Ckv[MROWS*128];
__device__ float g_q  [(size_t)B_*H_*S_*128];
__device__ float g_k  [(size_t)B_*H_*S_*128];
__device__ float g_vh [(size_t)B_*H_*S_*128];
__device__ float g_o  [MROWS*1536];
__device__ float g_xr [MROWS*768];
__device__ float g_Wr [2260992];
__device__ float g_freq[384];

// Wr offsets
#define WR_UQN 0
#define WR_UQR 98304
#define WR_UKN 196608
#define WR_UV  294912
#define WR_UKR 491520
#define WR_O   1081344

// ---------------- helpers ----------------
__device__ __forceinline__ float f2tf(float x) {
    asm("cvt.rna.tf32.f32 %0, %0;" : "+f"(x));
    return x;
}
__device__ __forceinline__ void mma8(float* d, const uint32_t* a, const uint32_t* b) {
    asm volatile(
        "mma.sync.aligned.m16n8k8.row.col.f32.tf32.tf32.f32 "
        "{%0,%1,%2,%3},{%4,%5,%6,%7},{%8,%9},{%0,%1,%2,%3};"
        : "+f"(d[0]), "+f"(d[1]), "+f"(d[2]), "+f"(d[3])
        : "r"(a[0]), "r"(a[1]), "r"(a[2]), "r"(a[3]), "r"(b[0]), "r"(b[1]));
}
__device__ __forceinline__ uint32_t smem_u32(const void* p) {
    return (uint32_t)__cvta_generic_to_shared(p);
}
__device__ __forceinline__ void cpasync16(uint32_t dst, const float* src) {
    asm volatile("cp.async.cg.shared.global [%0], [%1], 16;" :: "r"(dst), "l"(src));
}
// 128-float-wide tile, K-style swizzle (bits [4:2] ^= r&7)
__device__ __forceinline__ float ldsw(const float* base, int r, int c) {
    return base[((r << 7) + c) ^ ((r & 7) << 2)];
}
// 128-float-wide tile, V-style swizzle (bits [4:3] ^= r&3)
__device__ __forceinline__ float ldswv(const float* base, int r, int c) {
    return base[((r << 7) + c) ^ ((r & 3) << 3)];
}
// 32-float-wide tile (GEMM), swizzle bits [4:2] ^= r&7
__device__ __forceinline__ float ldsw32(const float* base, int r, int c) {
    return base[((r << 5) + c) ^ ((r & 7) << 2)];
}

// ---------------- freq table ----------------
__global__ void init_freq_kernel() {
    int i = threadIdx.x + blockIdx.x * blockDim.x;
    if (i < 384)
        g_freq[i] = (float)exp(-((double)(2 * i) / 768.0) * log(10000.0));
}

// ---------------- pre-round inputs to tf32 (RNA) ----------------
struct RTasks {
    const float* src[7];
    float* dst[7];
    int end4[7];
};
__global__ void preround_kernel(RTasks rt) {
    int idx = blockIdx.x * blockDim.x + threadIdx.x;
    if (idx >= rt.end4[6]) return;
    int ti = 0;
    while (idx >= rt.end4[ti]) ti++;
    int off = ti ? idx - rt.end4[ti - 1] : idx;
    float4 v = ((const float4*)rt.src[ti])[off];
    v.x = f2tf(v.x); v.y = f2tf(v.y); v.z = f2tf(v.z); v.w = f2tf(v.w);
    ((float4*)rt.dst[ti])[off] = v;
}

// ---------------- fp32 dual SGEMM for the two latent projections ----------------
#define GBM 128
#define GBK 16

__global__ __launch_bounds__(256)
void sgemm_bias_dual(const float* __restrict__ X,
                     const float* __restrict__ W1, const float* __restrict__ bias1, float* __restrict__ Y1,
                     const float* __restrict__ W2, const float* __restrict__ bias2, float* __restrict__ Y2,
                     int M, int K)
{
    const int N = 128;
    const float* W    = blockIdx.x ? W2 : W1;
    const float* bias = blockIdx.x ? bias2 : bias1;
    float*       Y    = blockIdx.x ? Y2 : Y1;

    __shared__ float As[GBK][GBM + 4];
    __shared__ float Bs[GBK][128 + 4];

    const int tid = threadIdx.x;
    const int tx = tid & 15;
    const int ty = tid >> 4;
    const int row0 = blockIdx.y * GBM;

    float acc[8][8];
#pragma unroll
    for (int i = 0; i < 8; i++)
#pragma unroll
        for (int j = 0; j < 8; j++) acc[i][j] = 0.f;

    for (int k0 = 0; k0 < K; k0 += GBK) {
#pragma unroll
        for (int it = 0; it < 2; it++) {
            int idx = tid + it * 256;
            int r = idx >> 2;
            int c4 = (idx & 3) << 2;
            float4 va = *(const float4*)&X[(size_t)(row0 + r) * K + k0 + c4];
            As[c4 + 0][r] = va.x; As[c4 + 1][r] = va.y;
            As[c4 + 2][r] = va.z; As[c4 + 3][r] = va.w;
            float4 vb = *(const float4*)&W[(size_t)r * K + k0 + c4];
            Bs[c4 + 0][r] = vb.x; Bs[c4 + 1][r] = vb.y;
            Bs[c4 + 2][r] = vb.z; Bs[c4 + 3][r] = vb.w;
        }
        __syncthreads();

#pragma unroll
        for (int kk = 0; kk < GBK; kk++) {
            float a[8], b[8];
            float4 a0 = *(const float4*)&As[kk][ty * 8];
            float4 a1 = *(const float4*)&As[kk][ty * 8 + 4];
            a[0]=a0.x; a[1]=a0.y; a[2]=a0.z; a[3]=a0.w;
            a[4]=a1.x; a[5]=a1.y; a[6]=a1.z; a[7]=a1.w;
            float4 b0 = *(const float4*)&Bs[kk][tx * 8];
            float4 b1 = *(const float4*)&Bs[kk][tx * 8 + 4];
            b[0]=b0.x; b[1]=b0.y; b[2]=b0.z; b[3]=b0.w;
            b[4]=b1.x; b[5]=b1.y; b[6]=b1.z; b[7]=b1.w;
#pragma unroll
            for (int i = 0; i < 8; i++)
#pragma unroll
                for (int j = 0; j < 8; j++)
                    acc[i][j] = fmaf(a[i], b[j], acc[i][j]);
        }
        __syncthreads();
    }

#pragma unroll
    for (int i = 0; i < 8; i++) {
        int m = row0 + ty * 8 + i;
#pragma unroll
        for (int j = 0; j < 8; j += 4) {
            int n = tx * 8 + j;
            float4 o;
            o.x = f2tf(acc[i][j + 0] + bias[n + 0]);
            o.y = f2tf(acc[i][j + 1] + bias[n + 1]);
            o.z = f2tf(acc[i][j + 2] + bias[n + 2]);
            o.w = f2tf(acc[i][j + 3] + bias[n + 3]);
            *(float4*)&Y[(size_t)m * N + n] = o;
        }
    }
}

// ---------------- multi-task TF32 GEMM, 3-stage cp.async, fused epilogues ----------------
// modes: 0 plain(bias)  1 q_nope  2 q_rope  3 k_nope  4 k_rope  5 v_scatter
struct GTask {
    const float* X; const float* W; const float* bias; float* Y;
    int K, mode, ntx, base;
};
struct GTasks { GTask t[6]; int n; int nblocks; };

#define MG_SMEM (3 * 8192 * 4)   // 96 KB

__global__ __launch_bounds__(256, 2)
void gemm_tf32_multi(GTasks tasks)
{
    extern __shared__ float sm[];

    int bid = blockIdx.x;
    if (bid >= tasks.nblocks) return;   // defensive bound
    int ti = 0;
#pragma unroll 1
    while (ti + 1 < tasks.n && bid >= tasks.t[ti + 1].base) ti++;
    const GTask tk = tasks.t[ti];
    int lb = bid - tk.base;
    int tilex = lb % tk.ntx;
    int tiley = lb / tk.ntx;

    const int tid  = threadIdx.x;
    const int lane = tid & 31;
    const int wid  = tid >> 5;
    const int g    = lane >> 2;
    const int t    = lane & 3;
    const int wm   = wid & 3;
    const int wn   = wid >> 2;
    const int K    = tk.K;
    const int kiters = K >> 5;

    const float* Xb = tk.X + (size_t)(tiley * 128) * K;
    const float* Wb = tk.W + (size_t)(tilex * 128) * K;

    float acc[2][8][4];
#pragma unroll
    for (int mt = 0; mt < 2; mt++)
#pragma unroll
        for (int nt = 0; nt < 8; nt++)
#pragma unroll
            for (int j = 0; j < 4; j++) acc[mt][nt][j] = 0.f;

    // prologue: stages 0,1
#pragma unroll
    for (int st = 0; st < 2; st++) {
        float* As = sm + st * 8192;
        float* Bs = As + 4096;
        int k0 = st * 32;
#pragma unroll
        for (int i = 0; i < 4; i++) {
            int ch = tid + i * 256;
            int r = ch >> 3, cc = ch & 7;
            int sch = (r << 3) + (cc ^ (r & 7));
            cpasync16(smem_u32(As + sch * 4), Xb + (size_t)r * K + k0 + cc * 4);
            cpasync16(smem_u32(Bs + sch * 4), Wb + (size_t)r * K + k0 + cc * 4);
        }
        asm volatile("cp.async.commit_group;");
    }

    for (int ki = 0; ki < kiters; ki++) {
        asm volatile("cp.async.wait_group 1;");
        __syncthreads();

        if (ki + 2 < kiters) {
            int st = (ki + 2) % 3;
            float* As = sm + st * 8192;
            float* Bs = As + 4096;
            int k0 = (ki + 2) * 32;
#pragma unroll
            for (int i = 0; i < 4; i++) {
                int ch = tid + i * 256;
                int r = ch >> 3, cc = ch & 7;
                int sch = (r << 3) + (cc ^ (r & 7));
                cpasync16(smem_u32(As + sch * 4), Xb + (size_t)r * K + k0 + cc * 4);
                cpasync16(smem_u32(Bs + sch * 4), Wb + (size_t)r * K + k0 + cc * 4);
            }
            asm volatile("cp.async.commit_group;");
        }

        const float* As = sm + (ki % 3) * 8192;
        const float* Bs = As + 4096;

#pragma unroll
        for (int kk = 0; kk < 4; kk++) {
            uint32_t af[2][4];
#pragma unroll
            for (int mt = 0; mt < 2; mt++) {
                int rb = wm * 32 + mt * 16;
                af[mt][0] = __float_as_uint(ldsw32(As, rb + g,     kk * 8 + t));
                af[mt][1] = __float_as_uint(ldsw32(As, rb + g + 8, kk * 8 + t));
                af[mt][2] = __float_as_uint(ldsw32(As, rb + g,     kk * 8 + t + 4));
                af[mt][3] = __float_as_uint(ldsw32(As, rb + g + 8, kk * 8 + t + 4));
            }
            uint32_t bf[8][2];
#pragma unroll
            for (int nt = 0; nt < 8; nt++) {
                int nb = wn * 64 + nt * 8;
                bf[nt][0] = __float_as_uint(ldsw32(Bs, nb + g, kk * 8 + t));
                bf[nt][1] = __float_as_uint(ldsw32(Bs, nb + g, kk * 8 + t + 4));
            }
#pragma unroll
            for (int mt = 0; mt < 2; mt++)
#pragma unroll
                for (int nt = 0; nt < 8; nt++)
                    mma8(acc[mt][nt], af[mt], bf[nt]);
        }
    }

    // ---- fused epilogue ----
    const float scale = 0.08838834764831845f;   // 1/sqrt(128)
    const int N = tk.ntx << 7;
    const int mode = tk.mode;

#pragma unroll
    for (int mt = 0; mt < 2; mt++) {
        int r0 = tiley * 128 + wm * 32 + mt * 16 + g;
#pragma unroll
        for (int nt = 0; nt < 8; nt++) {
            int n = tilex * 128 + wn * 64 + nt * 8 + 2 * t;
            float b0 = tk.bias[n], b1 = tk.bias[n + 1];
            float x0 = acc[mt][nt][0] + b0, y0 = acc[mt][nt][1] + b1;   // row r0
            float x1 = acc[mt][nt][2] + b0, y1 = acc[mt][nt][3] + b1;   // row r0+8

            if (mode == 0) {
                *(float2*)&tk.Y[(size_t)r0 * N + n]       = make_float2(x0, y0);
                *(float2*)&tk.Y[(size_t)(r0 + 8) * N + n] = make_float2(x1, y1);
            } else {
                int s0 = r0 & 2047;
                int f = n;
                if (mode == 2 || mode == 4) {   // rope
                    f = 768 + n;
                    float fr = g_freq[n >> 1];
                    float a0 = (float)s0 * fr;
                    float a1 = (float)(s0 + 8) * fr;
                    float c0 = cosf(a0), sn0 = sinf(a0);
                    float c1 = cosf(a1), sn1 = sinf(a1);
                    float tx0 = x0 * c0 - y0 * sn0, ty0 = x0 * sn0 + y0 * c0;
                    float tx1 = x1 * c1 - y1 * sn1, ty1 = x1 * sn1 + y1 * c1;
                    x0 = tx0; y0 = ty0; x1 = tx1; y1 = ty1;
                }
                if (mode <= 2) { x0 *= scale; y0 *= scale; x1 *= scale; y1 *= scale; }
                int h = f >> 7, d = f & 127;
                int b = r0 >> 11;
                size_t d0 = (((size_t)(b * H_ + h)) * S_ + s0) * 128 + d;
                *(float2*)&tk.Y[d0]            = make_float2(f2tf(x0), f2tf(y0));
                *(float2*)&tk.Y[d0 + 8 * 128]  = make_float2(f2tf(x1), f2tf(y1));
            }
        }
    }
}

// ---------------- TF32 flash attention, cp.async double-buffered ----------------
#define PST 68
#define ATT_SMEM_BYTES ((4*8192 + 128*PST) * 4)   // 165888

__global__ __launch_bounds__(256, 1)
void attn_tf32(const float* __restrict__ q, const float* __restrict__ k,
               const float* __restrict__ v, float* __restrict__ o)
{
    extern __shared__ float sm[];
    float* Ps = sm + 4 * 8192;

    const int tid  = threadIdx.x;
    const int lane = tid & 31;
    const int wid  = tid >> 5;
    const int g    = lane >> 2;
    const int t    = lane & 3;
    const int qt   = (S_ / 128 - 1) - blockIdx.x;
    const int bh   = blockIdx.y;
    const int b    = bh / H_, h = bh % H_;
    const size_t base = (size_t)bh * S_ * 128;

    // stage Q (pre-scaled + tf32-rounded), K-swizzle
    {
        const float* qg = q + base + (size_t)qt * 128 * 128;
#pragma unroll
        for (int i = 0; i < 16; i++) {
            int ch = tid + i * 256;
            int r  = ch >> 5;
            int sch = ch ^ (r & 7);
            cpasync16(smem_u32(sm + sch * 4), qg + ch * 4);
        }
        asm volatile("cp.async.commit_group;");
        asm volatile("cp.async.wait_group 0;");
        __syncthreads();
    }

    const int wr = wid * 16;
    uint32_t qf[16][4];
#pragma unroll
    for (int kk = 0; kk < 16; kk++) {
        qf[kk][0] = __float_as_uint(ldsw(sm, wr + g,     kk * 8 + t));
        qf[kk][1] = __float_as_uint(ldsw(sm, wr + g + 8, kk * 8 + t));
        qf[kk][2] = __float_as_uint(ldsw(sm, wr + g,     kk * 8 + t + 4));
        qf[kk][3] = __float_as_uint(ldsw(sm, wr + g + 8, kk * 8 + t + 4));
    }
    __syncthreads();

    float of[16][4];
#pragma unroll
    for (int nt = 0; nt < 16; nt++)
#pragma unroll
        for (int j = 0; j < 4; j++) of[nt][j] = 0.f;
    float m0 = -CUDART_INF_F, m1 = -CUDART_INF_F, l0 = 0.f, l1 = 0.f;

    const int row0g = qt * 128 + wr + g;
    const int row1g = row0g + 8;
    const int nkt = 2 * qt + 2;

    // prologue: tile 0 (K uses K-swizzle, V uses V-swizzle)
    {
        const float* kg = k + base;
        const float* vg = v + base;
#pragma unroll
        for (int i = 0; i < 8; i++) {
            int ch = tid + i * 256;
            int r  = ch >> 5;
            cpasync16(smem_u32(sm + (ch ^ (r & 7)) * 4),               kg + ch * 4);
            cpasync16(smem_u32(sm + 8192 + (ch ^ ((r & 3) << 1)) * 4), vg + ch * 4);
        }
        asm volatile("cp.async.commit_group;");
    }

    for (int kt = 0; kt < nkt; kt++) {
        asm volatile("cp.async.wait_group 0;");
        __syncthreads();

        if (kt + 1 < nkt) {
            float* dst = sm + ((kt + 1) & 1) * 16384;
            const float* kg = k + base + (size_t)(kt + 1) * 64 * 128;
            const float* vg = v + base + (size_t)(kt + 1) * 64 * 128;
#pragma unroll
            for (int i = 0; i < 8; i++) {
                int ch = tid + i * 256;
                int r  = ch >> 5;
                cpasync16(smem_u32(dst + (ch ^ (r & 7)) * 4),               kg + ch * 4);
                cpasync16(smem_u32(dst + 8192 + (ch ^ ((r & 3) << 1)) * 4), vg + ch * 4);
            }
            asm volatile("cp.async.commit_group;");
        }

        const float* Kb = sm + (kt & 1) * 16384;
        const float* Vb = Kb + 8192;

        // S = Q @ K^T
        float sc[8][4];
#pragma unroll
        for (int nt = 0; nt < 8; nt++)
#pragma unroll
            for (int j = 0; j < 4; j++) sc[nt][j] = 0.f;

#pragma unroll
        for (int kk = 0; kk < 16; kk++) {
#pragma unroll
            for (int nt = 0; nt < 8; nt++) {
                uint32_t bf[2];
                bf[0] = __float_as_uint(ldsw(Kb, nt * 8 + g, kk * 8 + t));
                bf[1] = __float_as_uint(ldsw(Kb, nt * 8 + g, kk * 8 + t + 4));
                mma8(sc[nt], qf[kk], bf);
            }
        }

        // causal mask
        if (kt >= 2 * qt) {
            int cbase = kt * 64 + 2 * t;
#pragma unroll
            for (int nt = 0; nt < 8; nt++) {
                int col = cbase + nt * 8;
                if (col     > row0g) sc[nt][0] = -CUDART_INF_F;
                if (col + 1 > row0g) sc[nt][1] = -CUDART_INF_F;
                if (col     > row1g) sc[nt][2] = -CUDART_INF_F;
                if (col + 1 > row1g) sc[nt][3] = -CUDART_INF_F;
            }
        }

        // online softmax
        float rmax0 = -CUDART_INF_F, rmax1 = -CUDART_INF_F;
#pragma unroll
        for (int nt = 0; nt < 8; nt++) {
            rmax0 = fmaxf(rmax0, fmaxf(sc[nt][0], sc[nt][1]));
            rmax1 = fmaxf(rmax1, fmaxf(sc[nt][2], sc[nt][3]));
        }
        rmax0 = fmaxf(rmax0, __shfl_xor_sync(0xffffffffu, rmax0, 1, 4));
        rmax0 = fmaxf(rmax0, __shfl_xor_sync(0xffffffffu, rmax0, 2, 4));
        rmax1 = fmaxf(rmax1, __shfl_xor_sync(0xffffffffu, rmax1, 1, 4));
        rmax1 = fmaxf(rmax1, __shfl_xor_sync(0xffffffffu, rmax1, 2, 4));

        float mn0 = fmaxf(m0, rmax0);
        float mn1 = fmaxf(m1, rmax1);
        float fac0 = __expf(m0 - mn0);
        float fac1 = __expf(m1 - mn1);
        m0 = mn0; m1 = mn1;

        float rs0 = 0.f, rs1 = 0.f;
#pragma unroll
        for (int nt = 0; nt < 8; nt++) {
            float p0 = __expf(sc[nt][0] - mn0);
            float p1 = __expf(sc[nt][1] - mn0);
            float p2 = __expf(sc[nt][2] - mn1);
            float p3 = __expf(sc[nt][3] - mn1);
            sc[nt][0] = p0; sc[nt][1] = p1; sc[nt][2] = p2; sc[nt][3] = p3;
            rs0 += p0 + p1; rs1 += p2 + p3;
        }
        rs0 += __shfl_xor_sync(0xffffffffu, rs0, 1, 4);
        rs0 += __shfl_xor_sync(0xffffffffu, rs0, 2, 4);
        rs1 += __shfl_xor_sync(0xffffffffu, rs1, 1, 4);
        rs1 += __shfl_xor_sync(0xffffffffu, rs1, 2, 4);
        l0 = l0 * fac0 + rs0;
        l1 = l1 * fac1 + rs1;

#pragma unroll
        for (int nt = 0; nt < 16; nt++) {
            of[nt][0] *= fac0; of[nt][1] *= fac0;
            of[nt][2] *= fac1; of[nt][3] *= fac1;
        }

        // P fragments -> smem (warp-private rows)
#pragma unroll
        for (int nt = 0; nt < 8; nt++) {
            int col = nt * 8 + 2 * t;
            *(float2*)&Ps[(wr + g)     * PST + col] = make_float2(f2tf(sc[nt][0]), f2tf(sc[nt][1]));
            *(float2*)&Ps[(wr + g + 8) * PST + col] = make_float2(f2tf(sc[nt][2]), f2tf(sc[nt][3]));
        }
        __syncwarp();

        // O += P @ V  (V via V-swizzle: conflict-free)
#pragma unroll
        for (int kk = 0; kk < 8; kk++) {
            uint32_t ap[4];
            ap[0] = __float_as_uint(Ps[(wr + g)     * PST + kk * 8 + t]);
            ap[1] = __float_as_uint(Ps[(wr + g + 8) * PST + kk * 8 + t]);
            ap[2] = __float_as_uint(Ps[(wr + g)     * PST + kk * 8 + t + 4]);
            ap[3] = __float_as_uint(Ps[(wr + g + 8) * PST + kk * 8 + t + 4]);
#pragma unroll
            for (int nt = 0; nt < 16; nt++) {
                uint32_t bf[2];
                bf[0] = __float_as_uint(ldswv(Vb, kk * 8 + t,     nt * 8 + g));
                bf[1] = __float_as_uint(ldswv(Vb, kk * 8 + t + 4, nt * 8 + g));
                mma8(of[nt], ap, bf);
            }
        }
        __syncthreads();
    }

    // epilogue: normalize, tf32-round (feeds out-proj), write [B,S,H*128]
    float inv0 = 1.0f / l0;
    float inv1 = 1.0f / l1;
    size_t orow0 = ((size_t)(b * S_ + row0g)) * 1536 + h * 128;
    size_t orow1 = ((size_t)(b * S_ + row1g)) * 1536 + h * 128;
#pragma unroll
    for (int nt = 0; nt < 16; nt++) {
        int col = nt * 8 + 2 * t;
        *(float2*)&o[orow0 + col] = make_float2(f2tf(of[nt][0] * inv0), f2tf(of[nt][1] * inv0));
        *(float2*)&o[orow1 + col] = make_float2(f2tf(of[nt][2] * inv1), f2tf(of[nt][3] * inv1));
    }
}

// ---------------- launch ----------------
extern "C" void kernel_launch(void* const* d_in, const int* in_sizes, int n_in,
                              void* d_out, int out_size)
{
    const float* x         = (const float*)d_in[0];
    const float* W_dkv     = (const float*)d_in[2];
    const float* b_dkv     = (const float*)d_in[3];
    const float* W_dq      = (const float*)d_in[4];
    const float* b_dq      = (const float*)d_in[5];
    const float* W_uk_nope = (const float*)d_in[6];
    const float* b_uk_nope = (const float*)d_in[7];
    const float* W_uv      = (const float*)d_in[8];
    const float* b_uv      = (const float*)d_in[9];
    const float* W_uq_nope = (const float*)d_in[10];
    const float* b_uq_nope = (const float*)d_in[11];
    const float* W_uq_rope = (const float*)d_in[12];
    const float* b_uq_rope = (const float*)d_in[13];
    const float* W_uk_rope = (const float*)d_in[14];
    const float* b_uk_rope = (const float*)d_in[15];
    const float* W_o       = (const float*)d_in[16];
    const float* b_o       = (const float*)d_in[17];
    float* out = (float*)d_out;

    float *Cq, *Ckv, *q, *k, *vh, *o, *xr, *Wr;
    cudaGetSymbolAddress((void**)&Cq,  g_Cq);
    cudaGetSymbolAddress((void**)&Ckv, g_Ckv);
    cudaGetSymbolAddress((void**)&q,   g_q);
    cudaGetSymbolAddress((void**)&k,   g_k);
    cudaGetSymbolAddress((void**)&vh,  g_vh);
    cudaGetSymbolAddress((void**)&o,   g_o);
    cudaGetSymbolAddress((void**)&xr,  g_xr);
    cudaGetSymbolAddress((void**)&Wr,  g_Wr);

    cudaFuncSetAttribute(attn_tf32, cudaFuncAttributeMaxDynamicSharedMemorySize, ATT_SMEM_BYTES);
    cudaFuncSetAttribute(gemm_tf32_multi, cudaFuncAttributeMaxDynamicSharedMemorySize, MG_SMEM);

    dim3 t(256);
    init_freq_kernel<<<2, 192>>>();

    // pre-round x and weights to tf32
    RTasks rt;
    rt.src[0] = x;         rt.dst[0] = xr;
    rt.src[1] = W_uq_nope; rt.dst[1] = Wr + WR_UQN;
    rt.src[2] = W_uq_rope; rt.dst[2] = Wr + WR_UQR;
    rt.src[3] = W_uk_nope; rt.dst[3] = Wr + WR_UKN;
    rt.src[4] = W_uv;      rt.dst[4] = Wr + WR_UV;
    rt.src[5] = W_uk_rope; rt.dst[5] = Wr + WR_UKR;
    rt.src[6] = W_o;       rt.dst[6] = Wr + WR_O;
    int counts[7] = {MROWS*768, 98304, 98304, 98304, 196608, 589824, 1179648};
    int acc4 = 0;
    for (int i = 0; i < 7; i++) { acc4 += counts[i] / 4; rt.end4[i] = acc4; }
    preround_kernel<<<(acc4 + 255) / 256, 256>>>(rt);

    // latent projections (fp32 accuracy anchor), rounded outputs
    sgemm_bias_dual<<<dim3(2, 64), t>>>(x, W_dq, b_dq, Cq, W_dkv, b_dkv, Ckv, MROWS, DM_);

    // all five up-projections fused (heavy-K k_rope first), epilogues do rope+scatter
    // blocks: k_rope 6*64=384 | v 12*64=768 | q_nope 384 | q_rope 384 | k_nope 384 => 2304
    GTasks gt;
    gt.n = 5;
    gt.nblocks = 2304;
    gt.t[0] = { xr,  Wr + WR_UKR, b_uk_rope, k,   768, 4,  6, 0    };  // k_rope
    gt.t[1] = { Ckv, Wr + WR_UV,  b_uv,      vh,  128, 5, 12, 384  };  // v
    gt.t[2] = { Cq,  Wr + WR_UQN, b_uq_nope, q,   128, 1,  6, 1152 };  // q_nope
    gt.t[3] = { Cq,  Wr + WR_UQR, b_uq_rope, q,   128, 2,  6, 1536 };  // q_rope
    gt.t[4] = { Ckv, Wr + WR_UKN, b_uk_nope, k,   128, 3,  6, 1920 };  // k_nope
    gemm_tf32_multi<<<2304, t, MG_SMEM>>>(gt);

    // tf32 flash attention
    attn_tf32<<<dim3(S_ / 128, B_ * H_), t, ATT_SMEM_BYTES>>>(q, k, vh, o);

    // output projection
    GTasks go;
    go.n = 1;
    go.nblocks = 384;
    go.t[0] = { o, Wr + WR_O, b_o, out, 1536, 0, 6, 0 };
    gemm_tf32_multi<<<384, t, MG_SMEM>>>(go);
}

// round 7
// speedup vs baseline: 5.8376x; 1.4669x over previous
#include <cuda_runtime.h>
#include <cuda_fp16.h>
#include <math_constants.h>
#include <math.h>
#include <stdint.h>

#define B_   4
#define S_   2048
#define H_   12
#define DM_  768
#define MROWS (B_*S_)   // 8192

// ---------------- scratch ----------------
__device__ __half g_Cq [MROWS*128];
__device__ __half g_Ckv[MROWS*128];
__device__ __half g_q  [(size_t)B_*H_*S_*128];
__device__ __half g_k  [(size_t)B_*H_*S_*128];
__device__ __half g_vh [(size_t)B_*H_*S_*128];
__device__ __half g_o  [MROWS*1536];
__device__ __half g_xh [MROWS*768];
__device__ __half g_Wh [2260992];
__device__ float  g_freq[384];

#define WR_UQN 0
#define WR_UQR 98304
#define WR_UKN 196608
#define WR_UV  294912
#define WR_UKR 491520
#define WR_O   1081344

// ---------------- helpers ----------------
__device__ __forceinline__ void mma16(float* d, const uint32_t* a, const uint32_t* b) {
    asm volatile(
        "mma.sync.aligned.m16n8k16.row.col.f32.f16.f16.f32 "
        "{%0,%1,%2,%3},{%4,%5,%6,%7},{%8,%9},{%0,%1,%2,%3};"
        : "+f"(d[0]), "+f"(d[1]), "+f"(d[2]), "+f"(d[3])
        : "r"(a[0]), "r"(a[1]), "r"(a[2]), "r"(a[3]), "r"(b[0]), "r"(b[1]));
}
__device__ __forceinline__ uint32_t smem_u32(const void* p) {
    return (uint32_t)__cvta_generic_to_shared(p);
}
__device__ __forceinline__ void cpasync16(uint32_t dst, const void* src) {
    asm volatile("cp.async.cg.shared.global [%0], [%1], 16;" :: "r"(dst), "l"(src));
}
__device__ __forceinline__ uint32_t packh2(float a, float b) {
    __half2 h = __floats2half2_rn(a, b);
    return *(uint32_t*)&h;
}

// ---------------- freq table ----------------
__global__ void init_freq_kernel() {
    int i = threadIdx.x + blockIdx.x * blockDim.x;
    if (i < 384)
        g_freq[i] = (float)exp(-((double)(2 * i) / 768.0) * log(10000.0));
}

// ---------------- convert fp32 -> fp16 ----------------
struct CTasks {
    const float* src[7];
    __half* dst[7];
    int end4[7];
};
__global__ void conv_half_kernel(CTasks ct) {
    int idx = blockIdx.x * blockDim.x + threadIdx.x;
    if (idx >= ct.end4[6]) return;
    int ti = 0;
    while (idx >= ct.end4[ti]) ti++;
    int off = ti ? idx - ct.end4[ti - 1] : idx;
    float4 v = ((const float4*)ct.src[ti])[off];
    __half2* d = (__half2*)ct.dst[ti];
    d[off * 2]     = __floats2half2_rn(v.x, v.y);
    d[off * 2 + 1] = __floats2half2_rn(v.z, v.w);
}

// ---------------- fp32 dual SGEMM for the two latent projections (half output) ----------------
#define GBM 128
#define GBK 16

__global__ __launch_bounds__(256)
void sgemm_bias_dual(const float* __restrict__ X,
                     const float* __restrict__ W1, const float* __restrict__ bias1, __half* __restrict__ Y1,
                     const float* __restrict__ W2, const float* __restrict__ bias2, __half* __restrict__ Y2,
                     int M, int K)
{
    const int N = 128;
    const float* W    = blockIdx.x ? W2 : W1;
    const float* bias = blockIdx.x ? bias2 : bias1;
    __half*      Y    = blockIdx.x ? Y2 : Y1;

    __shared__ float As[GBK][GBM + 4];
    __shared__ float Bs[GBK][128 + 4];

    const int tid = threadIdx.x;
    const int tx = tid & 15;
    const int ty = tid >> 4;
    const int row0 = blockIdx.y * GBM;

    float acc[8][8];
#pragma unroll
    for (int i = 0; i < 8; i++)
#pragma unroll
        for (int j = 0; j < 8; j++) acc[i][j] = 0.f;

    for (int k0 = 0; k0 < K; k0 += GBK) {
#pragma unroll
        for (int it = 0; it < 2; it++) {
            int idx = tid + it * 256;
            int r = idx >> 2;
            int c4 = (idx & 3) << 2;
            float4 va = *(const float4*)&X[(size_t)(row0 + r) * K + k0 + c4];
            As[c4 + 0][r] = va.x; As[c4 + 1][r] = va.y;
            As[c4 + 2][r] = va.z; As[c4 + 3][r] = va.w;
            float4 vb = *(const float4*)&W[(size_t)r * K + k0 + c4];
            Bs[c4 + 0][r] = vb.x; Bs[c4 + 1][r] = vb.y;
            Bs[c4 + 2][r] = vb.z; Bs[c4 + 3][r] = vb.w;
        }
        __syncthreads();

#pragma unroll
        for (int kk = 0; kk < GBK; kk++) {
            float a[8], b[8];
            float4 a0 = *(const float4*)&As[kk][ty * 8];
            float4 a1 = *(const float4*)&As[kk][ty * 8 + 4];
            a[0]=a0.x; a[1]=a0.y; a[2]=a0.z; a[3]=a0.w;
            a[4]=a1.x; a[5]=a1.y; a[6]=a1.z; a[7]=a1.w;
            float4 b0 = *(const float4*)&Bs[kk][tx * 8];
            float4 b1 = *(const float4*)&Bs[kk][tx * 8 + 4];
            b[0]=b0.x; b[1]=b0.y; b[2]=b0.z; b[3]=b0.w;
            b[4]=b1.x; b[5]=b1.y; b[6]=b1.z; b[7]=b1.w;
#pragma unroll
            for (int i = 0; i < 8; i++)
#pragma unroll
                for (int j = 0; j < 8; j++)
                    acc[i][j] = fmaf(a[i], b[j], acc[i][j]);
        }
        __syncthreads();
    }

#pragma unroll
    for (int i = 0; i < 8; i++) {
        int m = row0 + ty * 8 + i;
#pragma unroll
        for (int j = 0; j < 8; j += 4) {
            int n = tx * 8 + j;
            __half2* dst = (__half2*)&Y[(size_t)m * N + n];
            dst[0] = __floats2half2_rn(acc[i][j + 0] + bias[n + 0], acc[i][j + 1] + bias[n + 1]);
            dst[1] = __floats2half2_rn(acc[i][j + 2] + bias[n + 2], acc[i][j + 3] + bias[n + 3]);
        }
    }
}

// ---------------- multi-task FP16 GEMM, 3-stage cp.async, fused epilogues ----------------
// modes: 0 plain fp32 out  1 q_nope  2 q_rope  3 k_nope  4 k_rope  5 v_scatter
struct GTask {
    const void* X; const void* W; const float* bias; void* Y;
    int K, mode, ntx, base;
};
struct GTasks { GTask t[6]; int n; int nblocks; };

#define GST 20                    // smem row stride, uint32
#define MG_SMEM (3 * 5120 * 4)    // 61440 B

__global__ __launch_bounds__(256, 2)
void gemm_f16_multi(GTasks tasks)
{
    extern __shared__ uint32_t sm4[];

    int bid = blockIdx.x;
    if (bid >= tasks.nblocks) return;
    int ti = 0;
#pragma unroll 1
    while (ti + 1 < tasks.n && bid >= tasks.t[ti + 1].base) ti++;
    const GTask tk = tasks.t[ti];
    int lb = bid - tk.base;
    int tilex = lb % tk.ntx;
    int tiley = lb / tk.ntx;

    const int tid  = threadIdx.x;
    const int lane = tid & 31;
    const int wid  = tid >> 5;
    const int g    = lane >> 2;
    const int t    = lane & 3;
    const int wm   = wid & 3;
    const int wn   = wid >> 2;
    const int K    = tk.K;
    const int kiters = K >> 5;

    const __half* Xb = (const __half*)tk.X + (size_t)(tiley * 128) * K;
    const __half* Wb = (const __half*)tk.W + (size_t)(tilex * 128) * K;

    float acc[2][8][4];
#pragma unroll
    for (int mt = 0; mt < 2; mt++)
#pragma unroll
        for (int nt = 0; nt < 8; nt++)
#pragma unroll
            for (int j = 0; j < 4; j++) acc[mt][nt][j] = 0.f;

    // prologue: stages 0,1
#pragma unroll
    for (int st = 0; st < 2; st++) {
        uint32_t* As = sm4 + st * 5120;
        uint32_t* Bs = As + 2560;
        int k0 = st * 32;
#pragma unroll
        for (int i = 0; i < 4; i++) {
            int ch = tid + (i & 1) * 256;
            int r = ch >> 2, c = ch & 3;
            if (i < 2) cpasync16(smem_u32(As + r * GST + c * 4), Xb + (size_t)r * K + k0 + c * 8);
            else       cpasync16(smem_u32(Bs + r * GST + c * 4), Wb + (size_t)r * K + k0 + c * 8);
        }
        asm volatile("cp.async.commit_group;");
    }

    for (int ki = 0; ki < kiters; ki++) {
        asm volatile("cp.async.wait_group 1;");
        __syncthreads();

        if (ki + 2 < kiters) {
            int st = (ki + 2) % 3;
            uint32_t* As = sm4 + st * 5120;
            uint32_t* Bs = As + 2560;
            int k0 = (ki + 2) * 32;
#pragma unroll
            for (int i = 0; i < 4; i++) {
                int ch = tid + (i & 1) * 256;
                int r = ch >> 2, c = ch & 3;
                if (i < 2) cpasync16(smem_u32(As + r * GST + c * 4), Xb + (size_t)r * K + k0 + c * 8);
                else       cpasync16(smem_u32(Bs + r * GST + c * 4), Wb + (size_t)r * K + k0 + c * 8);
            }
            asm volatile("cp.async.commit_group;");
        }

        const uint32_t* As = sm4 + (ki % 3) * 5120;
        const uint32_t* Bs = As + 2560;

#pragma unroll
        for (int kk = 0; kk < 2; kk++) {
            uint32_t af[2][4];
#pragma unroll
            for (int mt = 0; mt < 2; mt++) {
                int rb = wm * 32 + mt * 16;
                af[mt][0] = As[(rb + g)     * GST + kk * 8 + t];
                af[mt][1] = As[(rb + g + 8) * GST + kk * 8 + t];
                af[mt][2] = As[(rb + g)     * GST + kk * 8 + t + 4];
                af[mt][3] = As[(rb + g + 8) * GST + kk * 8 + t + 4];
            }
            uint32_t bf[8][2];
#pragma unroll
            for (int nt = 0; nt < 8; nt++) {
                int nb = wn * 64 + nt * 8;
                bf[nt][0] = Bs[(nb + g) * GST + kk * 8 + t];
                bf[nt][1] = Bs[(nb + g) * GST + kk * 8 + t + 4];
            }
#pragma unroll
            for (int mt = 0; mt < 2; mt++)
#pragma unroll
                for (int nt = 0; nt < 8; nt++)
                    mma16(acc[mt][nt], af[mt], bf[nt]);
        }
    }

    // ---- fused epilogue ----
    const float scale = 0.08838834764831845f;   // 1/sqrt(128)
    const int N = tk.ntx << 7;
    const int mode = tk.mode;

#pragma unroll
    for (int mt = 0; mt < 2; mt++) {
        int r0 = tiley * 128 + wm * 32 + mt * 16 + g;
#pragma unroll
        for (int nt = 0; nt < 8; nt++) {
            int n = tilex * 128 + wn * 64 + nt * 8 + 2 * t;
            float b0 = tk.bias[n], b1 = tk.bias[n + 1];
            float x0 = acc[mt][nt][0] + b0, y0 = acc[mt][nt][1] + b1;
            float x1 = acc[mt][nt][2] + b0, y1 = acc[mt][nt][3] + b1;

            if (mode == 0) {
                float* Yf = (float*)tk.Y;
                *(float2*)&Yf[(size_t)r0 * N + n]       = make_float2(x0, y0);
                *(float2*)&Yf[(size_t)(r0 + 8) * N + n] = make_float2(x1, y1);
            } else {
                int s0 = r0 & 2047;
                int f = n;
                if (mode == 2 || mode == 4) {   // rope
                    f = 768 + n;
                    float fr = g_freq[n >> 1];
                    float a0 = (float)s0 * fr;
                    float a1 = (float)(s0 + 8) * fr;
                    float c0 = cosf(a0), sn0 = sinf(a0);
                    float c1 = cosf(a1), sn1 = sinf(a1);
                    float tx0 = x0 * c0 - y0 * sn0, ty0 = x0 * sn0 + y0 * c0;
                    float tx1 = x1 * c1 - y1 * sn1, ty1 = x1 * sn1 + y1 * c1;
                    x0 = tx0; y0 = ty0; x1 = tx1; y1 = ty1;
                }
                if (mode <= 2) { x0 *= scale; y0 *= scale; x1 *= scale; y1 *= scale; }
                int h = f >> 7, d = f & 127;
                int b = r0 >> 11;
                __half* Yh = (__half*)tk.Y;
                size_t d0 = (((size_t)(b * H_ + h)) * S_ + s0) * 128 + d;
                *(__half2*)&Yh[d0]           = __floats2half2_rn(x0, y0);
                *(__half2*)&Yh[d0 + 8 * 128] = __floats2half2_rn(x1, y1);
            }
        }
    }
}

// ---------------- FP16 flash attention, cp.async double-buffered, in-smem V transpose ----------------
// smem (uint32): K0[64*68] K1[64*68] Vn0[64*68] Vn1[64*68] Vt[128*36] Ps[128*36]
#define AKST 68
#define VTST 36
#define PSST 36
#define OFF_K0  0
#define OFF_K1  4352
#define OFF_VN0 8704
#define OFF_VN1 13056
#define OFF_VT  17408
#define OFF_PS  22016
#define ATT_SMEM_BYTES (26624 * 4)   // 106496

__global__ __launch_bounds__(256, 1)
void attn_f16(const __half* __restrict__ q, const __half* __restrict__ k,
              const __half* __restrict__ v, __half* __restrict__ o)
{
    extern __shared__ uint32_t sm4[];

    const int tid  = threadIdx.x;
    const int lane = tid & 31;
    const int wid  = tid >> 5;
    const int g    = lane >> 2;
    const int t    = lane & 3;
    const int qt   = (S_ / 128 - 1) - blockIdx.x;   // big tiles first
    const int bh   = blockIdx.y;
    const int b    = bh / H_, h = bh % H_;
    const size_t base = (size_t)bh * S_ * 128;

    // ---- stage Q (pre-scaled fp16), fill qf (overlays K0/K1 region) ----
    {
        const __half* qg = q + base + (size_t)qt * 128 * 128;
#pragma unroll
        for (int i = 0; i < 8; i++) {
            int ch = tid + i * 256;
            int r = ch >> 4, c4 = (ch & 15) << 2;
            cpasync16(smem_u32(sm4 + r * AKST + c4), qg + (size_t)r * 128 + ((ch & 15) << 3));
        }
        asm volatile("cp.async.commit_group;");
        asm volatile("cp.async.wait_group 0;");
        __syncthreads();
    }

    const int wr = wid * 16;
    uint32_t qf[8][4];
#pragma unroll
    for (int kk = 0; kk < 8; kk++) {
        qf[kk][0] = sm4[(wr + g)     * AKST + kk * 8 + t];
        qf[kk][1] = sm4[(wr + g + 8) * AKST + kk * 8 + t];
        qf[kk][2] = sm4[(wr + g)     * AKST + kk * 8 + t + 4];
        qf[kk][3] = sm4[(wr + g + 8) * AKST + kk * 8 + t + 4];
    }
    __syncthreads();

    float of[16][4];
#pragma unroll
    for (int nt = 0; nt < 16; nt++)
#pragma unroll
        for (int j = 0; j < 4; j++) of[nt][j] = 0.f;
    float m0 = -CUDART_INF_F, m1 = -CUDART_INF_F, l0 = 0.f, l1 = 0.f;

    const int row0g = qt * 128 + wr + g;
    const int row1g = row0g + 8;
    const int nkt = 2 * qt + 2;

    // prologue: tile 0
    {
        const __half* kg = k + base;
        const __half* vg = v + base;
#pragma unroll
        for (int i = 0; i < 8; i++) {
            int ch = tid + (i & 3) * 256;
            int r = ch >> 4, c4 = (ch & 15) << 2, c8 = (ch & 15) << 3;
            if (i < 4) cpasync16(smem_u32(sm4 + OFF_K0 + r * AKST + c4),  kg + (size_t)r * 128 + c8);
            else       cpasync16(smem_u32(sm4 + OFF_VN0 + r * AKST + c4), vg + (size_t)r * 128 + c8);
        }
        asm volatile("cp.async.commit_group;");
    }

    uint32_t* Vt  = sm4 + OFF_VT;
    uint32_t* Psu = sm4 + OFF_PS;

    for (int kt = 0; kt < nkt; kt++) {
        asm volatile("cp.async.wait_group 0;");
        __syncthreads();

        if (kt + 1 < nkt) {
            const __half* kg = k + base + (size_t)(kt + 1) * 64 * 128;
            const __half* vg = v + base + (size_t)(kt + 1) * 64 * 128;
            uint32_t* Kd = sm4 + (((kt + 1) & 1) ? OFF_K1 : OFF_K0);
            uint32_t* Vd = sm4 + (((kt + 1) & 1) ? OFF_VN1 : OFF_VN0);
#pragma unroll
            for (int i = 0; i < 8; i++) {
                int ch = tid + (i & 3) * 256;
                int r = ch >> 4, c4 = (ch & 15) << 2, c8 = (ch & 15) << 3;
                if (i < 4) cpasync16(smem_u32(Kd + r * AKST + c4), kg + (size_t)r * 128 + c8);
                else       cpasync16(smem_u32(Vd + r * AKST + c4), vg + (size_t)r * 128 + c8);
            }
            asm volatile("cp.async.commit_group;");
        }

        // ---- transpose Vn(kt) -> Vt, ALL 64 uint32 cols (dims 0..127) ----
        {
            const uint32_t* Vn = sm4 + ((kt & 1) ? OFF_VN1 : OFF_VN0);
#pragma unroll
            for (int j = 0; j < 4; j++) {
                int kp = wid * 4 + j;                 // key pair 0..31
                int cs = kp ^ lane;                   // col swizzle: (row>>1)&31 == lane for both halves
#pragma unroll
                for (int hf = 0; hf < 2; hf++) {
                    int col = lane + hf * 32;         // uint32 col 0..63 (dims 2col, 2col+1)
                    uint32_t s0 = Vn[(2 * kp)     * AKST + col];
                    uint32_t s1 = Vn[(2 * kp + 1) * AKST + col];
                    uint32_t ev = __byte_perm(s0, s1, 0x5410);
                    uint32_t od = __byte_perm(s0, s1, 0x7632);
                    Vt[(2 * col)     * VTST + cs] = ev;
                    Vt[(2 * col + 1) * VTST + cs] = od;
                }
            }
        }
        __syncthreads();

        const uint32_t* Kb = sm4 + ((kt & 1) ? OFF_K1 : OFF_K0);

        // ---- S = Q @ K^T ----
        float sc[8][4];
#pragma unroll
        for (int nt = 0; nt < 8; nt++)
#pragma unroll
            for (int j = 0; j < 4; j++) sc[nt][j] = 0.f;

#pragma unroll
        for (int kk = 0; kk < 8; kk++) {
#pragma unroll
            for (int nt = 0; nt < 8; nt++) {
                uint32_t bf[2];
                bf[0] = Kb[(nt * 8 + g) * AKST + kk * 8 + t];
                bf[1] = Kb[(nt * 8 + g) * AKST + kk * 8 + t + 4];
                mma16(sc[nt], qf[kk], bf);
            }
        }

        // ---- causal mask ----
        if (kt >= 2 * qt) {
            int cbase = kt * 64 + 2 * t;
#pragma unroll
            for (int nt = 0; nt < 8; nt++) {
                int col = cbase + nt * 8;
                if (col     > row0g) sc[nt][0] = -CUDART_INF_F;
                if (col + 1 > row0g) sc[nt][1] = -CUDART_INF_F;
                if (col     > row1g) sc[nt][2] = -CUDART_INF_F;
                if (col + 1 > row1g) sc[nt][3] = -CUDART_INF_F;
            }
        }

        // ---- online softmax ----
        float rmax0 = -CUDART_INF_F, rmax1 = -CUDART_INF_F;
#pragma unroll
        for (int nt = 0; nt < 8; nt++) {
            rmax0 = fmaxf(rmax0, fmaxf(sc[nt][0], sc[nt][1]));
            rmax1 = fmaxf(rmax1, fmaxf(sc[nt][2], sc[nt][3]));
        }
        rmax0 = fmaxf(rmax0, __shfl_xor_sync(0xffffffffu, rmax0, 1, 4));
        rmax0 = fmaxf(rmax0, __shfl_xor_sync(0xffffffffu, rmax0, 2, 4));
        rmax1 = fmaxf(rmax1, __shfl_xor_sync(0xffffffffu, rmax1, 1, 4));
        rmax1 = fmaxf(rmax1, __shfl_xor_sync(0xffffffffu, rmax1, 2, 4));

        float mn0 = fmaxf(m0, rmax0);
        float mn1 = fmaxf(m1, rmax1);
        float fac0 = __expf(m0 - mn0);
        float fac1 = __expf(m1 - mn1);
        m0 = mn0; m1 = mn1;

        float rs0 = 0.f, rs1 = 0.f;
#pragma unroll
        for (int nt = 0; nt < 8; nt++) {
            float p0 = __expf(sc[nt][0] - mn0);
            float p1 = __expf(sc[nt][1] - mn0);
            float p2 = __expf(sc[nt][2] - mn1);
            float p3 = __expf(sc[nt][3] - mn1);
            sc[nt][0] = p0; sc[nt][1] = p1; sc[nt][2] = p2; sc[nt][3] = p3;
            rs0 += p0 + p1; rs1 += p2 + p3;
        }
        rs0 += __shfl_xor_sync(0xffffffffu, rs0, 1, 4);
        rs0 += __shfl_xor_sync(0xffffffffu, rs0, 2, 4);
        rs1 += __shfl_xor_sync(0xffffffffu, rs1, 1, 4);
        rs1 += __shfl_xor_sync(0xffffffffu, rs1, 2, 4);
        l0 = l0 * fac0 + rs0;
        l1 = l1 * fac1 + rs1;

#pragma unroll
        for (int nt = 0; nt < 16; nt++) {
            of[nt][0] *= fac0; of[nt][1] *= fac0;
            of[nt][2] *= fac1; of[nt][3] *= fac1;
        }

        // ---- P -> smem as fp16 (warp-private rows) ----
#pragma unroll
        for (int nt = 0; nt < 8; nt++) {
            Psu[(wr + g)     * PSST + nt * 4 + t] = packh2(sc[nt][0], sc[nt][1]);
            Psu[(wr + g + 8) * PSST + nt * 4 + t] = packh2(sc[nt][2], sc[nt][3]);
        }
        __syncwarp();

        // ---- O += P @ V (Vt: pairs along keys, swizzled) ----
#pragma unroll
        for (int kk = 0; kk < 4; kk++) {
            uint32_t ap[4];
            ap[0] = Psu[(wr + g)     * PSST + kk * 8 + t];
            ap[1] = Psu[(wr + g + 8) * PSST + kk * 8 + t];
            ap[2] = Psu[(wr + g)     * PSST + kk * 8 + t + 4];
            ap[3] = Psu[(wr + g + 8) * PSST + kk * 8 + t + 4];
#pragma unroll
            for (int nt = 0; nt < 16; nt++) {
                int n0 = nt * 8 + g;
                int swz = (n0 >> 1) & 31;
                uint32_t bf[2];
                bf[0] = Vt[n0 * VTST + ((kk * 8 + t)     ^ swz)];
                bf[1] = Vt[n0 * VTST + ((kk * 8 + t + 4) ^ swz)];
                mma16(of[nt], ap, bf);
            }
        }
    }

    // ---- epilogue: normalize, write half to [B,S,H*128] ----
    float inv0 = 1.0f / l0;
    float inv1 = 1.0f / l1;
    size_t orow0 = ((size_t)(b * S_ + row0g)) * 1536 + h * 128;
    size_t orow1 = ((size_t)(b * S_ + row1g)) * 1536 + h * 128;
#pragma unroll
    for (int nt = 0; nt < 16; nt++) {
        int col = nt * 8 + 2 * t;
        *(__half2*)&o[orow0 + col] = __floats2half2_rn(of[nt][0] * inv0, of[nt][1] * inv0);
        *(__half2*)&o[orow1 + col] = __floats2half2_rn(of[nt][2] * inv1, of[nt][3] * inv1);
    }
}

// ---------------- launch ----------------
extern "C" void kernel_launch(void* const* d_in, const int* in_sizes, int n_in,
                              void* d_out, int out_size)
{
    const float* x         = (const float*)d_in[0];
    const float* W_dkv     = (const float*)d_in[2];
    const float* b_dkv     = (const float*)d_in[3];
    const float* W_dq      = (const float*)d_in[4];
    const float* b_dq      = (const float*)d_in[5];
    const float* W_uk_nope = (const float*)d_in[6];
    const float* b_uk_nope = (const float*)d_in[7];
    const float* W_uv      = (const float*)d_in[8];
    const float* b_uv      = (const float*)d_in[9];
    const float* W_uq_nope = (const float*)d_in[10];
    const float* b_uq_nope = (const float*)d_in[11];
    const float* W_uq_rope = (const float*)d_in[12];
    const float* b_uq_rope = (const float*)d_in[13];
    const float* W_uk_rope = (const float*)d_in[14];
    const float* b_uk_rope = (const float*)d_in[15];
    const float* W_o       = (const float*)d_in[16];
    const float* b_o       = (const float*)d_in[17];
    float* out = (float*)d_out;

    __half *Cq, *Ckv, *q, *k, *vh, *o, *xh, *Wh;
    cudaGetSymbolAddress((void**)&Cq,  g_Cq);
    cudaGetSymbolAddress((void**)&Ckv, g_Ckv);
    cudaGetSymbolAddress((void**)&q,   g_q);
    cudaGetSymbolAddress((void**)&k,   g_k);
    cudaGetSymbolAddress((void**)&vh,  g_vh);
    cudaGetSymbolAddress((void**)&o,   g_o);
    cudaGetSymbolAddress((void**)&xh,  g_xh);
    cudaGetSymbolAddress((void**)&Wh,  g_Wh);

    cudaFuncSetAttribute(attn_f16, cudaFuncAttributeMaxDynamicSharedMemorySize, ATT_SMEM_BYTES);
    cudaFuncSetAttribute(gemm_f16_multi, cudaFuncAttributeMaxDynamicSharedMemorySize, MG_SMEM);

    dim3 t(256);
    init_freq_kernel<<<2, 192>>>();

    // convert x and fp16-consumed weights
    CTasks ct;
    ct.src[0] = x;         ct.dst[0] = xh;
    ct.src[1] = W_uq_nope; ct.dst[1] = Wh + WR_UQN;
    ct.src[2] = W_uq_rope; ct.dst[2] = Wh + WR_UQR;
    ct.src[3] = W_uk_nope; ct.dst[3] = Wh + WR_UKN;
    ct.src[4] = W_uv;      ct.dst[4] = Wh + WR_UV;
    ct.src[5] = W_uk_rope; ct.dst[5] = Wh + WR_UKR;
    ct.src[6] = W_o;       ct.dst[6] = Wh + WR_O;
    int counts[7] = {MROWS*768, 98304, 98304, 98304, 196608, 589824, 1179648};
    int acc4 = 0;
    for (int i = 0; i < 7; i++) { acc4 += counts[i] / 4; ct.end4[i] = acc4; }
    conv_half_kernel<<<(acc4 + 255) / 256, 256>>>(ct);

    // latent projections (fp32 accuracy anchor), half outputs
    sgemm_bias_dual<<<dim3(2, 64), t>>>(x, W_dq, b_dq, Cq, W_dkv, b_dkv, Ckv, MROWS, DM_);

    // five up-projections fused (heavy-K k_rope first); epilogues do rope+scatter
    GTasks gt;
    gt.n = 5;
    gt.nblocks = 2304;
    gt.t[0] = { xh,  Wh + WR_UKR, b_uk_rope, k,   768, 4,  6, 0    };
    gt.t[1] = { Ckv, Wh + WR_UV,  b_uv,      vh,  128, 5, 12, 384  };
    gt.t[2] = { Cq,  Wh + WR_UQN, b_uq_nope, q,   128, 1,  6, 1152 };
    gt.t[3] = { Cq,  Wh + WR_UQR, b_uq_rope, q,   128, 2,  6, 1536 };
    gt.t[4] = { Ckv, Wh + WR_UKN, b_uk_nope, k,   128, 3,  6, 1920 };
    gemm_f16_multi<<<2304, t, MG_SMEM>>>(gt);

    // fp16 flash attention
    attn_f16<<<dim3(S_ / 128, B_ * H_), t, ATT_SMEM_BYTES>>>(q, k, vh, o);

    // output projection (fp32 result)
    GTasks go;
    go.n = 1;
    go.nblocks = 384;
    go.t[0] = { o, Wh + WR_O, b_o, out, 1536, 0, 6, 0 };
    gemm_f16_multi<<<384, t, MG_SMEM>>>(go);
}

// round 8
// speedup vs baseline: 6.7929x; 1.1636x over previous
#include <cuda_runtime.h>
#include <cuda_fp16.h>
#include <math_constants.h>
#include <math.h>
#include <stdint.h>

#define B_   4
#define S_   2048
#define H_   12
#define DM_  768
#define MROWS (B_*S_)   // 8192

// ---------------- scratch ----------------
__device__ __half g_Cq [MROWS*128];
__device__ __half g_Ckv[MROWS*128];
__device__ __half g_q  [(size_t)B_*H_*S_*128];
__device__ __half g_k  [(size_t)B_*H_*S_*128];
__device__ __half g_vh [(size_t)B_*H_*S_*128];
__device__ __half g_o  [MROWS*1536];
__device__ __half g_xh [MROWS*768];
__device__ __half g_Wh [2457600];
__device__ float  g_freq[384];

#define WR_UQN 0
#define WR_UQR 98304
#define WR_UKN 196608
#define WR_UV  294912
#define WR_UKR 491520
#define WR_O   1081344
#define WR_DQ  2260992
#define WR_DKV 2359296

// ---------------- helpers ----------------
__device__ __forceinline__ void mma16(float* d, const uint32_t* a, const uint32_t* b) {
    asm volatile(
        "mma.sync.aligned.m16n8k16.row.col.f32.f16.f16.f32 "
        "{%0,%1,%2,%3},{%4,%5,%6,%7},{%8,%9},{%0,%1,%2,%3};"
        : "+f"(d[0]), "+f"(d[1]), "+f"(d[2]), "+f"(d[3])
        : "r"(a[0]), "r"(a[1]), "r"(a[2]), "r"(a[3]), "r"(b[0]), "r"(b[1]));
}
__device__ __forceinline__ uint32_t smem_u32(const void* p) {
    return (uint32_t)__cvta_generic_to_shared(p);
}
__device__ __forceinline__ void cpasync16(uint32_t dst, const void* src) {
    asm volatile("cp.async.cg.shared.global [%0], [%1], 16;" :: "r"(dst), "l"(src));
}
__device__ __forceinline__ uint32_t packh2(float a, float b) {
    __half2 h = __floats2half2_rn(a, b);
    return *(uint32_t*)&h;
}

// ---------------- freq table ----------------
__global__ void init_freq_kernel() {
    int i = threadIdx.x + blockIdx.x * blockDim.x;
    if (i < 384)
        g_freq[i] = (float)exp(-((double)(2 * i) / 768.0) * log(10000.0));
}

// ---------------- convert fp32 -> fp16 ----------------
struct CTasks {
    const float* src[9];
    __half* dst[9];
    int end4[9];
};
__global__ void conv_half_kernel(CTasks ct) {
    int idx = blockIdx.x * blockDim.x + threadIdx.x;
    if (idx >= ct.end4[8]) return;
    int ti = 0;
    while (idx >= ct.end4[ti]) ti++;
    int off = ti ? idx - ct.end4[ti - 1] : idx;
    float4 v = ((const float4*)ct.src[ti])[off];
    __half2* d = (__half2*)ct.dst[ti];
    d[off * 2]     = __floats2half2_rn(v.x, v.y);
    d[off * 2 + 1] = __floats2half2_rn(v.z, v.w);
}

// ---------------- multi-task FP16 GEMM, TBK=64, 3-stage cp.async, fused epilogues ----------------
// modes: 0 plain fp32 out  1 q_nope  2 q_rope  3 k_nope  4 k_rope  5 v_scatter  6 plain half out
struct GTask {
    const void* X; const void* W; const float* bias; void* Y;
    int K, mode, ntx, base;
};
struct GTasks { GTask t[6]; int n; int nblocks; };

#define GST 36                     // smem row stride, uint32 (32 data + 4 pad)
#define STG_U32 4608               // 128 * 36 per matrix per stage
#define MG_SMEM (3 * 2 * STG_U32 * 4)   // 110592 B

__global__ __launch_bounds__(256, 2)
void gemm_f16_multi(GTasks tasks)
{
    extern __shared__ uint32_t sm4[];

    int bid = blockIdx.x;
    if (bid >= tasks.nblocks) return;
    int ti = 0;
#pragma unroll 1
    while (ti + 1 < tasks.n && bid >= tasks.t[ti + 1].base) ti++;
    const GTask tk = tasks.t[ti];
    int lb = bid - tk.base;
    int tilex = lb % tk.ntx;
    int tiley = lb / tk.ntx;

    const int tid  = threadIdx.x;
    const int lane = tid & 31;
    const int wid  = tid >> 5;
    const int g    = lane >> 2;
    const int t    = lane & 3;
    const int wm   = wid & 3;
    const int wn   = wid >> 2;
    const int K    = tk.K;
    const int kiters = K >> 6;

    const __half* Xb = (const __half*)tk.X + (size_t)(tiley * 128) * K;
    const __half* Wb = (const __half*)tk.W + (size_t)(tilex * 128) * K;

    float acc[2][8][4];
#pragma unroll
    for (int mt = 0; mt < 2; mt++)
#pragma unroll
        for (int nt = 0; nt < 8; nt++)
#pragma unroll
            for (int j = 0; j < 4; j++) acc[mt][nt][j] = 0.f;

    // prologue: stages 0,1 (K >= 128 always -> kiters >= 2)
#pragma unroll
    for (int st = 0; st < 2; st++) {
        uint32_t* As = sm4 + st * (2 * STG_U32);
        uint32_t* Bs = As + STG_U32;
        int k0 = st * 64;
#pragma unroll
        for (int i = 0; i < 8; i++) {
            int ch = tid + (i & 3) * 256;     // 0..1023
            int r = ch >> 3, c = ch & 7;
            if (i < 4) cpasync16(smem_u32(As + r * GST + c * 4), Xb + (size_t)r * K + k0 + c * 8);
            else       cpasync16(smem_u32(Bs + r * GST + c * 4), Wb + (size_t)r * K + k0 + c * 8);
        }
        asm volatile("cp.async.commit_group;");
    }

    for (int ki = 0; ki < kiters; ki++) {
        if (ki + 1 < kiters) asm volatile("cp.async.wait_group 1;");
        else                 asm volatile("cp.async.wait_group 0;");
        __syncthreads();

        if (ki + 2 < kiters) {
            int st = (ki + 2) % 3;
            uint32_t* As = sm4 + st * (2 * STG_U32);
            uint32_t* Bs = As + STG_U32;
            int k0 = (ki + 2) * 64;
#pragma unroll
            for (int i = 0; i < 8; i++) {
                int ch = tid + (i & 3) * 256;
                int r = ch >> 3, c = ch & 7;
                if (i < 4) cpasync16(smem_u32(As + r * GST + c * 4), Xb + (size_t)r * K + k0 + c * 8);
                else       cpasync16(smem_u32(Bs + r * GST + c * 4), Wb + (size_t)r * K + k0 + c * 8);
            }
            asm volatile("cp.async.commit_group;");
        }

        const uint32_t* As = sm4 + (ki % 3) * (2 * STG_U32);
        const uint32_t* Bs = As + STG_U32;

#pragma unroll
        for (int kk = 0; kk < 4; kk++) {
            uint32_t af[2][4];
#pragma unroll
            for (int mt = 0; mt < 2; mt++) {
                int rb = wm * 32 + mt * 16;
                af[mt][0] = As[(rb + g)     * GST + kk * 8 + t];
                af[mt][1] = As[(rb + g + 8) * GST + kk * 8 + t];
                af[mt][2] = As[(rb + g)     * GST + kk * 8 + t + 4];
                af[mt][3] = As[(rb + g + 8) * GST + kk * 8 + t + 4];
            }
            uint32_t bf[8][2];
#pragma unroll
            for (int nt = 0; nt < 8; nt++) {
                int nb = wn * 64 + nt * 8;
                bf[nt][0] = Bs[(nb + g) * GST + kk * 8 + t];
                bf[nt][1] = Bs[(nb + g) * GST + kk * 8 + t + 4];
            }
#pragma unroll
            for (int mt = 0; mt < 2; mt++)
#pragma unroll
                for (int nt = 0; nt < 8; nt++)
                    mma16(acc[mt][nt], af[mt], bf[nt]);
        }
    }

    // ---- fused epilogue ----
    const float scale = 0.08838834764831845f;   // 1/sqrt(128)
    const int N = tk.ntx << 7;
    const int mode = tk.mode;

#pragma unroll
    for (int mt = 0; mt < 2; mt++) {
        int r0 = tiley * 128 + wm * 32 + mt * 16 + g;
#pragma unroll
        for (int nt = 0; nt < 8; nt++) {
            int n = tilex * 128 + wn * 64 + nt * 8 + 2 * t;
            float b0 = tk.bias[n], b1 = tk.bias[n + 1];
            float x0 = acc[mt][nt][0] + b0, y0 = acc[mt][nt][1] + b1;
            float x1 = acc[mt][nt][2] + b0, y1 = acc[mt][nt][3] + b1;

            if (mode == 0) {
                float* Yf = (float*)tk.Y;
                *(float2*)&Yf[(size_t)r0 * N + n]       = make_float2(x0, y0);
                *(float2*)&Yf[(size_t)(r0 + 8) * N + n] = make_float2(x1, y1);
            } else if (mode == 6) {
                __half* Yh = (__half*)tk.Y;
                *(__half2*)&Yh[(size_t)r0 * N + n]       = __floats2half2_rn(x0, y0);
                *(__half2*)&Yh[(size_t)(r0 + 8) * N + n] = __floats2half2_rn(x1, y1);
            } else {
                int s0 = r0 & 2047;
                int f = n;
                if (mode == 2 || mode == 4) {   // rope
                    f = 768 + n;
                    float fr = g_freq[n >> 1];
                    float a0 = (float)s0 * fr;
                    float a1 = (float)(s0 + 8) * fr;
                    float c0 = cosf(a0), sn0 = sinf(a0);
                    float c1 = cosf(a1), sn1 = sinf(a1);
                    float tx0 = x0 * c0 - y0 * sn0, ty0 = x0 * sn0 + y0 * c0;
                    float tx1 = x1 * c1 - y1 * sn1, ty1 = x1 * sn1 + y1 * c1;
                    x0 = tx0; y0 = ty0; x1 = tx1; y1 = ty1;
                }
                if (mode <= 2) { x0 *= scale; y0 *= scale; x1 *= scale; y1 *= scale; }
                int h = f >> 7, d = f & 127;
                int b = r0 >> 11;
                __half* Yh = (__half*)tk.Y;
                size_t d0 = (((size_t)(b * H_ + h)) * S_ + s0) * 128 + d;
                *(__half2*)&Yh[d0]           = __floats2half2_rn(x0, y0);
                *(__half2*)&Yh[d0 + 8 * 128] = __floats2half2_rn(x1, y1);
            }
        }
    }
}

// ---------------- FP16 flash attention, cp.async double-buffered, in-smem V transpose ----------------
// smem (uint32): K0[64*68] K1[64*68] Vn0[64*68] Vn1[64*68] Vt[128*36] Ps[128*36]
#define AKST 68
#define VTST 36
#define PSST 36
#define OFF_K0  0
#define OFF_K1  4352
#define OFF_VN0 8704
#define OFF_VN1 13056
#define OFF_VT  17408
#define OFF_PS  22016
#define ATT_SMEM_BYTES (26624 * 4)   // 106496

__global__ __launch_bounds__(256, 1)
void attn_f16(const __half* __restrict__ q, const __half* __restrict__ k,
              const __half* __restrict__ v, __half* __restrict__ o)
{
    extern __shared__ uint32_t sm4[];

    const int tid  = threadIdx.x;
    const int lane = tid & 31;
    const int wid  = tid >> 5;
    const int g    = lane >> 2;
    const int t    = lane & 3;
    const int qt   = (S_ / 128 - 1) - blockIdx.x;   // big tiles first
    const int bh   = blockIdx.y;
    const int b    = bh / H_, h = bh % H_;
    const size_t base = (size_t)bh * S_ * 128;

    // ---- stage Q (pre-scaled fp16), fill qf (overlays K0/K1 region) ----
    {
        const __half* qg = q + base + (size_t)qt * 128 * 128;
#pragma unroll
        for (int i = 0; i < 8; i++) {
            int ch = tid + i * 256;
            int r = ch >> 4, c4 = (ch & 15) << 2;
            cpasync16(smem_u32(sm4 + r * AKST + c4), qg + (size_t)r * 128 + ((ch & 15) << 3));
        }
        asm volatile("cp.async.commit_group;");
        asm volatile("cp.async.wait_group 0;");
        __syncthreads();
    }

    const int wr = wid * 16;
    uint32_t qf[8][4];
#pragma unroll
    for (int kk = 0; kk < 8; kk++) {
        qf[kk][0] = sm4[(wr + g)     * AKST + kk * 8 + t];
        qf[kk][1] = sm4[(wr + g + 8) * AKST + kk * 8 + t];
        qf[kk][2] = sm4[(wr + g)     * AKST + kk * 8 + t + 4];
        qf[kk][3] = sm4[(wr + g + 8) * AKST + kk * 8 + t + 4];
    }
    __syncthreads();

    float of[16][4];
#pragma unroll
    for (int nt = 0; nt < 16; nt++)
#pragma unroll
        for (int j = 0; j < 4; j++) of[nt][j] = 0.f;
    float m0 = -CUDART_INF_F, m1 = -CUDART_INF_F, l0 = 0.f, l1 = 0.f;

    const int row0g = qt * 128 + wr + g;
    const int row1g = row0g + 8;
    const int nkt = 2 * qt + 2;

    // prologue: tile 0
    {
        const __half* kg = k + base;
        const __half* vg = v + base;
#pragma unroll
        for (int i = 0; i < 8; i++) {
            int ch = tid + (i & 3) * 256;
            int r = ch >> 4, c4 = (ch & 15) << 2, c8 = (ch & 15) << 3;
            if (i < 4) cpasync16(smem_u32(sm4 + OFF_K0 + r * AKST + c4),  kg + (size_t)r * 128 + c8);
            else       cpasync16(smem_u32(sm4 + OFF_VN0 + r * AKST + c4), vg + (size_t)r * 128 + c8);
        }
        asm volatile("cp.async.commit_group;");
    }

    uint32_t* Vt  = sm4 + OFF_VT;
    uint32_t* Psu = sm4 + OFF_PS;

    for (int kt = 0; kt < nkt; kt++) {
        asm volatile("cp.async.wait_group 0;");
        __syncthreads();

        if (kt + 1 < nkt) {
            const __half* kg = k + base + (size_t)(kt + 1) * 64 * 128;
            const __half* vg = v + base + (size_t)(kt + 1) * 64 * 128;
            uint32_t* Kd = sm4 + (((kt + 1) & 1) ? OFF_K1 : OFF_K0);
            uint32_t* Vd = sm4 + (((kt + 1) & 1) ? OFF_VN1 : OFF_VN0);
#pragma unroll
            for (int i = 0; i < 8; i++) {
                int ch = tid + (i & 3) * 256;
                int r = ch >> 4, c4 = (ch & 15) << 2, c8 = (ch & 15) << 3;
                if (i < 4) cpasync16(smem_u32(Kd + r * AKST + c4), kg + (size_t)r * 128 + c8);
                else       cpasync16(smem_u32(Vd + r * AKST + c4), vg + (size_t)r * 128 + c8);
            }
            asm volatile("cp.async.commit_group;");
        }

        // ---- transpose Vn(kt) -> Vt, all 64 uint32 cols ----
        {
            const uint32_t* Vn = sm4 + ((kt & 1) ? OFF_VN1 : OFF_VN0);
#pragma unroll
            for (int j = 0; j < 4; j++) {
                int kp = wid * 4 + j;
                int cs = kp ^ lane;
#pragma unroll
                for (int hf = 0; hf < 2; hf++) {
                    int col = lane + hf * 32;
                    uint32_t s0 = Vn[(2 * kp)     * AKST + col];
                    uint32_t s1 = Vn[(2 * kp + 1) * AKST + col];
                    uint32_t ev = __byte_perm(s0, s1, 0x5410);
                    uint32_t od = __byte_perm(s0, s1, 0x7632);
                    Vt[(2 * col)     * VTST + cs] = ev;
                    Vt[(2 * col + 1) * VTST + cs] = od;
                }
            }
        }
        __syncthreads();

        const uint32_t* Kb = sm4 + ((kt & 1) ? OFF_K1 : OFF_K0);

        // ---- S = Q @ K^T ----
        float sc[8][4];
#pragma unroll
        for (int nt = 0; nt < 8; nt++)
#pragma unroll
            for (int j = 0; j < 4; j++) sc[nt][j] = 0.f;

#pragma unroll
        for (int kk = 0; kk < 8; kk++) {
#pragma unroll
            for (int nt = 0; nt < 8; nt++) {
                uint32_t bf[2];
                bf[0] = Kb[(nt * 8 + g) * AKST + kk * 8 + t];
                bf[1] = Kb[(nt * 8 + g) * AKST + kk * 8 + t + 4];
                mma16(sc[nt], qf[kk], bf);
            }
        }

        // ---- causal mask ----
        if (kt >= 2 * qt) {
            int cbase = kt * 64 + 2 * t;
#pragma unroll
            for (int nt = 0; nt < 8; nt++) {
                int col = cbase + nt * 8;
                if (col     > row0g) sc[nt][0] = -CUDART_INF_F;
                if (col + 1 > row0g) sc[nt][1] = -CUDART_INF_F;
                if (col     > row1g) sc[nt][2] = -CUDART_INF_F;
                if (col + 1 > row1g) sc[nt][3] = -CUDART_INF_F;
            }
        }

        // ---- online softmax ----
        float rmax0 = -CUDART_INF_F, rmax1 = -CUDART_INF_F;
#pragma unroll
        for (int nt = 0; nt < 8; nt++) {
            rmax0 = fmaxf(rmax0, fmaxf(sc[nt][0], sc[nt][1]));
            rmax1 = fmaxf(rmax1, fmaxf(sc[nt][2], sc[nt][3]));
        }
        rmax0 = fmaxf(rmax0, __shfl_xor_sync(0xffffffffu, rmax0, 1, 4));
        rmax0 = fmaxf(rmax0, __shfl_xor_sync(0xffffffffu, rmax0, 2, 4));
        rmax1 = fmaxf(rmax1, __shfl_xor_sync(0xffffffffu, rmax1, 1, 4));
        rmax1 = fmaxf(rmax1, __shfl_xor_sync(0xffffffffu, rmax1, 2, 4));

        float mn0 = fmaxf(m0, rmax0);
        float mn1 = fmaxf(m1, rmax1);
        float fac0 = __expf(m0 - mn0);
        float fac1 = __expf(m1 - mn1);
        m0 = mn0; m1 = mn1;

        float rs0 = 0.f, rs1 = 0.f;
#pragma unroll
        for (int nt = 0; nt < 8; nt++) {
            float p0 = __expf(sc[nt][0] - mn0);
            float p1 = __expf(sc[nt][1] - mn0);
            float p2 = __expf(sc[nt][2] - mn1);
            float p3 = __expf(sc[nt][3] - mn1);
            sc[nt][0] = p0; sc[nt][1] = p1; sc[nt][2] = p2; sc[nt][3] = p3;
            rs0 += p0 + p1; rs1 += p2 + p3;
        }
        rs0 += __shfl_xor_sync(0xffffffffu, rs0, 1, 4);
        rs0 += __shfl_xor_sync(0xffffffffu, rs0, 2, 4);
        rs1 += __shfl_xor_sync(0xffffffffu, rs1, 1, 4);
        rs1 += __shfl_xor_sync(0xffffffffu, rs1, 2, 4);
        l0 = l0 * fac0 + rs0;
        l1 = l1 * fac1 + rs1;

#pragma unroll
        for (int nt = 0; nt < 16; nt++) {
            of[nt][0] *= fac0; of[nt][1] *= fac0;
            of[nt][2] *= fac1; of[nt][3] *= fac1;
        }

        // ---- P -> smem as fp16 (warp-private rows) ----
#pragma unroll
        for (int nt = 0; nt < 8; nt++) {
            Psu[(wr + g)     * PSST + nt * 4 + t] = packh2(sc[nt][0], sc[nt][1]);
            Psu[(wr + g + 8) * PSST + nt * 4 + t] = packh2(sc[nt][2], sc[nt][3]);
        }
        __syncwarp();

        // ---- O += P @ V ----
#pragma unroll
        for (int kk = 0; kk < 4; kk++) {
            uint32_t ap[4];
            ap[0] = Psu[(wr + g)     * PSST + kk * 8 + t];
            ap[1] = Psu[(wr + g + 8) * PSST + kk * 8 + t];
            ap[2] = Psu[(wr + g)     * PSST + kk * 8 + t + 4];
            ap[3] = Psu[(wr + g + 8) * PSST + kk * 8 + t + 4];
#pragma unroll
            for (int nt = 0; nt < 16; nt++) {
                int n0 = nt * 8 + g;
                int swz = (n0 >> 1) & 31;
                uint32_t bf[2];
                bf[0] = Vt[n0 * VTST + ((kk * 8 + t)     ^ swz)];
                bf[1] = Vt[n0 * VTST + ((kk * 8 + t + 4) ^ swz)];
                mma16(of[nt], ap, bf);
            }
        }
    }

    // ---- epilogue: normalize, write half to [B,S,H*128] ----
    float inv0 = 1.0f / l0;
    float inv1 = 1.0f / l1;
    size_t orow0 = ((size_t)(b * S_ + row0g)) * 1536 + h * 128;
    size_t orow1 = ((size_t)(b * S_ + row1g)) * 1536 + h * 128;
#pragma unroll
    for (int nt = 0; nt < 16; nt++) {
        int col = nt * 8 + 2 * t;
        *(__half2*)&o[orow0 + col] = __floats2half2_rn(of[nt][0] * inv0, of[nt][1] * inv0);
        *(__half2*)&o[orow1 + col] = __floats2half2_rn(of[nt][2] * inv1, of[nt][3] * inv1);
    }
}

// ---------------- launch ----------------
extern "C" void kernel_launch(void* const* d_in, const int* in_sizes, int n_in,
                              void* d_out, int out_size)
{
    const float* x         = (const float*)d_in[0];
    const float* W_dkv     = (const float*)d_in[2];
    const float* b_dkv     = (const float*)d_in[3];
    const float* W_dq      = (const float*)d_in[4];
    const float* b_dq      = (const float*)d_in[5];
    const float* W_uk_nope = (const float*)d_in[6];
    const float* b_uk_nope = (const float*)d_in[7];
    const float* W_uv      = (const float*)d_in[8];
    const float* b_uv      = (const float*)d_in[9];
    const float* W_uq_nope = (const float*)d_in[10];
    const float* b_uq_nope = (const float*)d_in[11];
    const float* W_uq_rope = (const float*)d_in[12];
    const float* b_uq_rope = (const float*)d_in[13];
    const float* W_uk_rope = (const float*)d_in[14];
    const float* b_uk_rope = (const float*)d_in[15];
    const float* W_o       = (const float*)d_in[16];
    const float* b_o       = (const float*)d_in[17];
    float* out = (float*)d_out;

    __half *Cq, *Ckv, *q, *k, *vh, *o, *xh, *Wh;
    cudaGetSymbolAddress((void**)&Cq,  g_Cq);
    cudaGetSymbolAddress((void**)&Ckv, g_Ckv);
    cudaGetSymbolAddress((void**)&q,   g_q);
    cudaGetSymbolAddress((void**)&k,   g_k);
    cudaGetSymbolAddress((void**)&vh,  g_vh);
    cudaGetSymbolAddress((void**)&o,   g_o);
    cudaGetSymbolAddress((void**)&xh,  g_xh);
    cudaGetSymbolAddress((void**)&Wh,  g_Wh);

    cudaFuncSetAttribute(attn_f16, cudaFuncAttributeMaxDynamicSharedMemorySize, ATT_SMEM_BYTES);
    cudaFuncSetAttribute(gemm_f16_multi, cudaFuncAttributeMaxDynamicSharedMemorySize, MG_SMEM);

    dim3 t(256);
    init_freq_kernel<<<2, 192>>>();

    // convert x and all fp16-consumed weights
    CTasks ct;
    ct.src[0] = x;         ct.dst[0] = xh;
    ct.src[1] = W_uq_nope; ct.dst[1] = Wh + WR_UQN;
    ct.src[2] = W_uq_rope; ct.dst[2] = Wh + WR_UQR;
    ct.src[3] = W_uk_nope; ct.dst[3] = Wh + WR_UKN;
    ct.src[4] = W_uv;      ct.dst[4] = Wh + WR_UV;
    ct.src[5] = W_uk_rope; ct.dst[5] = Wh + WR_UKR;
    ct.src[6] = W_o;       ct.dst[6] = Wh + WR_O;
    ct.src[7] = W_dq;      ct.dst[7] = Wh + WR_DQ;
    ct.src[8] = W_dkv;     ct.dst[8] = Wh + WR_DKV;
    int counts[9] = {MROWS*768, 98304, 98304, 98304, 196608, 589824, 1179648, 98304, 98304};
    int acc4 = 0;
    for (int i = 0; i < 9; i++) { acc4 += counts[i] / 4; ct.end4[i] = acc4; }
    conv_half_kernel<<<(acc4 + 255) / 256, 256>>>(ct);

    // latent projections in fp16 (half outputs)
    GTasks gl;
    gl.n = 2;
    gl.nblocks = 128;
    gl.t[0] = { xh, Wh + WR_DQ,  b_dq,  Cq,  768, 6, 1, 0  };
    gl.t[1] = { xh, Wh + WR_DKV, b_dkv, Ckv, 768, 6, 1, 64 };
    gemm_f16_multi<<<128, t, MG_SMEM>>>(gl);

    // five up-projections fused (heavy-K k_rope first); epilogues do rope+scatter
    GTasks gt;
    gt.n = 5;
    gt.nblocks = 2304;
    gt.t[0] = { xh,  Wh + WR_UKR, b_uk_rope, k,   768, 4,  6, 0    };
    gt.t[1] = { Ckv, Wh + WR_UV,  b_uv,      vh,  128, 5, 12, 384  };
    gt.t[2] = { Cq,  Wh + WR_UQN, b_uq_nope, q,   128, 1,  6, 1152 };
    gt.t[3] = { Cq,  Wh + WR_UQR, b_uq_rope, q,   128, 2,  6, 1536 };
    gt.t[4] = { Ckv, Wh + WR_UKN, b_uk_nope, k,   128, 3,  6, 1920 };
    gemm_f16_multi<<<2304, t, MG_SMEM>>>(gt);

    // fp16 flash attention
    attn_f16<<<dim3(S_ / 128, B_ * H_), t, ATT_SMEM_BYTES>>>(q, k, vh, o);

    // output projection (fp32 result)
    GTasks go;
    go.n = 1;
    go.nblocks = 384;
    go.t[0] = { o, Wh + WR_O, b_o, out, 1536, 0, 6, 0 };
    gemm_f16_multi<<<384, t, MG_SMEM>>>(go);
}

// round 10
// speedup vs baseline: 8.2895x; 1.2203x over previous
#include <cuda_runtime.h>
#include <cuda_fp16.h>
#include <math_constants.h>
#include <math.h>
#include <stdint.h>

#define B_   4
#define S_   2048
#define H_   12
#define DM_  768
#define MROWS (B_*S_)   // 8192

// ---------------- scratch ----------------
__device__ __half g_Cq [MROWS*128];
__device__ __half g_Ckv[MROWS*128];
__device__ __half g_q  [(size_t)B_*H_*S_*128];
__device__ __half g_k  [(size_t)B_*H_*S_*128];
__device__ __half g_vh [(size_t)B_*H_*S_*128];
__device__ __half g_o  [MROWS*1536];
__device__ __half g_xh [MROWS*768];
__device__ __half g_Wh [2457600];
__device__ float  g_freq[384];

#define WR_UQN 0
#define WR_UQR 98304
#define WR_UKN 196608
#define WR_UV  294912
#define WR_UKR 491520
#define WR_O   1081344
#define WR_DQ  2260992
#define WR_DKV 2359296

// ---------------- helpers ----------------
__device__ __forceinline__ void mma16(float* d, const uint32_t* a, const uint32_t* b) {
    asm volatile(
        "mma.sync.aligned.m16n8k16.row.col.f32.f16.f16.f32 "
        "{%0,%1,%2,%3},{%4,%5,%6,%7},{%8,%9},{%0,%1,%2,%3};"
        : "+f"(d[0]), "+f"(d[1]), "+f"(d[2]), "+f"(d[3])
        : "r"(a[0]), "r"(a[1]), "r"(a[2]), "r"(a[3]), "r"(b[0]), "r"(b[1]));
}
__device__ __forceinline__ uint32_t smem_u32(const void* p) {
    return (uint32_t)__cvta_generic_to_shared(p);
}
__device__ __forceinline__ void cpasync16(uint32_t dst, const void* src) {
    asm volatile("cp.async.cg.shared.global [%0], [%1], 16;" :: "r"(dst), "l"(src));
}
__device__ __forceinline__ uint32_t packh2(float a, float b) {
    __half2 h = __floats2half2_rn(a, b);
    return *(uint32_t*)&h;
}
__device__ __forceinline__ void ldsm_x4(uint32_t* r, uint32_t addr) {
    asm volatile("ldmatrix.sync.aligned.m8n8.x4.shared.b16 {%0,%1,%2,%3}, [%4];"
        : "=r"(r[0]), "=r"(r[1]), "=r"(r[2]), "=r"(r[3]) : "r"(addr));
}
__device__ __forceinline__ void ldsm_x4t(uint32_t* r, uint32_t addr) {
    asm volatile("ldmatrix.sync.aligned.m8n8.x4.trans.shared.b16 {%0,%1,%2,%3}, [%4];"
        : "=r"(r[0]), "=r"(r[1]), "=r"(r[2]), "=r"(r[3]) : "r"(addr));
}

// ---------------- freq table ----------------
__global__ void init_freq_kernel() {
    int i = threadIdx.x + blockIdx.x * blockDim.x;
    if (i < 384)
        g_freq[i] = (float)exp(-((double)(2 * i) / 768.0) * log(10000.0));
}

// ---------------- convert fp32 -> fp16 ----------------
struct CTasks {
    const float* src[9];
    __half* dst[9];
    int end4[9];
};
__global__ void conv_half_kernel(CTasks ct) {
    int idx = blockIdx.x * blockDim.x + threadIdx.x;
    if (idx >= ct.end4[8]) return;
    int ti = 0;
    while (idx >= ct.end4[ti]) ti++;
    int off = ti ? idx - ct.end4[ti - 1] : idx;
    float4 v = ((const float4*)ct.src[ti])[off];
    __half2* d = (__half2*)ct.dst[ti];
    d[off * 2]     = __floats2half2_rn(v.x, v.y);
    d[off * 2 + 1] = __floats2half2_rn(v.z, v.w);
}

// ---------------- multi-task FP16 GEMM, TBK=64, 3-stage cp.async, ldmatrix fragments ----------------
// modes: 0 plain fp32 out  1 q_nope  2 q_rope  3 k_nope  4 k_rope  5 v_scatter  6 plain half out
struct GTask {
    const void* X; const void* W; const float* bias; void* Y;
    int K, mode, ntx, base;
};
struct GTasks { GTask t[6]; int n; int nblocks; };

#define GST 36                     // smem row stride, uint32 (32 data + 4 pad)
#define STG_U32 4608               // 128 * 36 per matrix per stage
#define MG_SMEM (3 * 2 * STG_U32 * 4)   // 110592 B

__global__ __launch_bounds__(256, 2)
void gemm_f16_multi(GTasks tasks)
{
    extern __shared__ uint32_t sm4[];
    const uint32_t sb = smem_u32(sm4);

    int bid = blockIdx.x;
    if (bid >= tasks.nblocks) return;
    int ti = 0;
#pragma unroll 1
    while (ti + 1 < tasks.n && bid >= tasks.t[ti + 1].base) ti++;
    const GTask tk = tasks.t[ti];
    int lb = bid - tk.base;
    int tilex = lb % tk.ntx;
    int tiley = lb / tk.ntx;

    const int tid  = threadIdx.x;
    const int lane = tid & 31;
    const int wid  = tid >> 5;
    const int g    = lane >> 2;
    const int t    = lane & 3;
    const int wm   = wid & 3;
    const int wn   = wid >> 2;
    const int K    = tk.K;
    const int kiters = K >> 6;

    // ldmatrix per-lane address constants (uint32 units)
    const int lm = lane >> 3, lr = lane & 7;
    const int constA = ((lm & 1) * 8 + lr) * GST + (lm >> 1) * 4;   // A: m1=+8rows, m2=+chunk
    const int constB = ((lm >> 1) * 8 + lr) * GST + (lm & 1) * 4;   // B: m1=+chunk, m2=+8rows

    const __half* Xb = (const __half*)tk.X + (size_t)(tiley * 128) * K;
    const __half* Wb = (const __half*)tk.W + (size_t)(tilex * 128) * K;

    float acc[2][8][4];
#pragma unroll
    for (int mt = 0; mt < 2; mt++)
#pragma unroll
        for (int nt = 0; nt < 8; nt++)
#pragma unroll
            for (int j = 0; j < 4; j++) acc[mt][nt][j] = 0.f;

    // prologue: stages 0,1
#pragma unroll
    for (int st = 0; st < 2; st++) {
        uint32_t As = sb + st * (2 * STG_U32) * 4;
        uint32_t Bs = As + STG_U32 * 4;
        int k0 = st * 64;
#pragma unroll
        for (int i = 0; i < 8; i++) {
            int ch = tid + (i & 3) * 256;     // 0..1023
            int r = ch >> 3, c = ch & 7;
            if (i < 4) cpasync16(As + (r * GST + c * 4) * 4, Xb + (size_t)r * K + k0 + c * 8);
            else       cpasync16(Bs + (r * GST + c * 4) * 4, Wb + (size_t)r * K + k0 + c * 8);
        }
        asm volatile("cp.async.commit_group;");
    }

    for (int ki = 0; ki < kiters; ki++) {
        if (ki + 1 < kiters) asm volatile("cp.async.wait_group 1;");
        else                 asm volatile("cp.async.wait_group 0;");
        __syncthreads();

        if (ki + 2 < kiters) {
            int st = (ki + 2) % 3;
            uint32_t As = sb + st * (2 * STG_U32) * 4;
            uint32_t Bs = As + STG_U32 * 4;
            int k0 = (ki + 2) * 64;
#pragma unroll
            for (int i = 0; i < 8; i++) {
                int ch = tid + (i & 3) * 256;
                int r = ch >> 3, c = ch & 7;
                if (i < 4) cpasync16(As + (r * GST + c * 4) * 4, Xb + (size_t)r * K + k0 + c * 8);
                else       cpasync16(Bs + (r * GST + c * 4) * 4, Wb + (size_t)r * K + k0 + c * 8);
            }
            asm volatile("cp.async.commit_group;");
        }

        const uint32_t As = sb + (ki % 3) * (2 * STG_U32) * 4;
        const uint32_t Bs = As + STG_U32 * 4;

#pragma unroll
        for (int kk = 0; kk < 4; kk++) {
            uint32_t af[2][4];
            ldsm_x4(af[0], As + (constA + (wm * 32)      * GST + kk * 8) * 4);
            ldsm_x4(af[1], As + (constA + (wm * 32 + 16) * GST + kk * 8) * 4);
#pragma unroll
            for (int ntp = 0; ntp < 4; ntp++) {
                uint32_t bf[4];
                ldsm_x4(bf, Bs + (constB + (wn * 64 + ntp * 16) * GST + kk * 8) * 4);
                mma16(acc[0][2 * ntp],     af[0], bf);
                mma16(acc[0][2 * ntp + 1], af[0], bf + 2);
                mma16(acc[1][2 * ntp],     af[1], bf);
                mma16(acc[1][2 * ntp + 1], af[1], bf + 2);
            }
        }
    }

    // ---- fused epilogue ----
    const float scale = 0.08838834764831845f;   // 1/sqrt(128)
    const int N = tk.ntx << 7;
    const int mode = tk.mode;

#pragma unroll
    for (int mt = 0; mt < 2; mt++) {
        int r0 = tiley * 128 + wm * 32 + mt * 16 + g;
#pragma unroll
        for (int nt = 0; nt < 8; nt++) {
            int n = tilex * 128 + wn * 64 + nt * 8 + 2 * t;
            float b0 = tk.bias[n], b1 = tk.bias[n + 1];
            float x0 = acc[mt][nt][0] + b0, y0 = acc[mt][nt][1] + b1;
            float x1 = acc[mt][nt][2] + b0, y1 = acc[mt][nt][3] + b1;

            if (mode == 0) {
                float* Yf = (float*)tk.Y;
                *(float2*)&Yf[(size_t)r0 * N + n]       = make_float2(x0, y0);
                *(float2*)&Yf[(size_t)(r0 + 8) * N + n] = make_float2(x1, y1);
            } else if (mode == 6) {
                __half* Yh = (__half*)tk.Y;
                *(__half2*)&Yh[(size_t)r0 * N + n]       = __floats2half2_rn(x0, y0);
                *(__half2*)&Yh[(size_t)(r0 + 8) * N + n] = __floats2half2_rn(x1, y1);
            } else {
                int s0 = r0 & 2047;
                int f = n;
                if (mode == 2 || mode == 4) {   // rope
                    f = 768 + n;
                    float fr = g_freq[n >> 1];
                    float a0 = (float)s0 * fr;
                    float a1 = (float)(s0 + 8) * fr;
                    float c0 = cosf(a0), sn0 = sinf(a0);
                    float c1 = cosf(a1), sn1 = sinf(a1);
                    float tx0 = x0 * c0 - y0 * sn0, ty0 = x0 * sn0 + y0 * c0;
                    float tx1 = x1 * c1 - y1 * sn1, ty1 = x1 * sn1 + y1 * c1;
                    x0 = tx0; y0 = ty0; x1 = tx1; y1 = ty1;
                }
                if (mode <= 2) { x0 *= scale; y0 *= scale; x1 *= scale; y1 *= scale; }
                int h = f >> 7, d = f & 127;
                int b = r0 >> 11;
                __half* Yh = (__half*)tk.Y;
                size_t d0 = (((size_t)(b * H_ + h)) * S_ + s0) * 128 + d;
                *(__half2*)&Yh[d0]           = __floats2half2_rn(x0, y0);
                *(__half2*)&Yh[d0 + 8 * 128] = __floats2half2_rn(x1, y1);
            }
        }
    }
}

// ---------------- FP16 flash attention: ldmatrix fragments, register-resident P ----------------
// smem (uint32): K0[64*68] K1[64*68] Vn0[64*68] Vn1[64*68]
#define AKST 68
#define OFF_K0  0
#define OFF_K1  4352
#define OFF_VN0 8704
#define OFF_VN1 13056
#define ATT_SMEM_BYTES (17408 * 4)   // 69632

__global__ __launch_bounds__(256, 1)
void attn_f16(const __half* __restrict__ q, const __half* __restrict__ k,
              const __half* __restrict__ v, __half* __restrict__ o)
{
    extern __shared__ uint32_t sm4[];
    const uint32_t sb = smem_u32(sm4);

    const int tid  = threadIdx.x;
    const int lane = tid & 31;
    const int wid  = tid >> 5;
    const int g    = lane >> 2;
    const int t    = lane & 3;
    const int qt   = (S_ / 128 - 1) - blockIdx.x;   // big tiles first
    const int bh   = blockIdx.y;
    const int b    = bh / H_, h = bh % H_;
    const size_t base = (size_t)bh * S_ * 128;

    // ldmatrix per-lane constants (uint32 units, stride AKST)
    const int lm = lane >> 3, lr = lane & 7;
    const int constA = ((lm & 1) * 8 + lr) * AKST + (lm >> 1) * 4;   // A-pattern (Q) & V-trans
    const int constB = ((lm >> 1) * 8 + lr) * AKST + (lm & 1) * 4;   // B-pattern (K)

    // ---- stage Q (pre-scaled fp16), extract qf via ldmatrix (overlays K0/K1) ----
    {
        const __half* qg = q + base + (size_t)qt * 128 * 128;
#pragma unroll
        for (int i = 0; i < 8; i++) {
            int ch = tid + i * 256;
            int r = ch >> 4, c4 = (ch & 15) << 2;
            cpasync16(sb + (r * AKST + c4) * 4, qg + (size_t)r * 128 + ((ch & 15) << 3));
        }
        asm volatile("cp.async.commit_group;");
        asm volatile("cp.async.wait_group 0;");
        __syncthreads();
    }

    const int wr = wid * 16;
    uint32_t qf[8][4];
#pragma unroll
    for (int kk = 0; kk < 8; kk++)
        ldsm_x4(qf[kk], sb + (constA + wr * AKST + kk * 8) * 4);
    __syncthreads();

    float of[16][4];
#pragma unroll
    for (int nt = 0; nt < 16; nt++)
#pragma unroll
        for (int j = 0; j < 4; j++) of[nt][j] = 0.f;
    float m0 = -CUDART_INF_F, m1 = -CUDART_INF_F, l0 = 0.f, l1 = 0.f;

    const int row0g = qt * 128 + wr + g;
    const int row1g = row0g + 8;
    const int nkt = 2 * qt + 2;

    // prologue: tile 0
    {
        const __half* kg = k + base;
        const __half* vg = v + base;
#pragma unroll
        for (int i = 0; i < 8; i++) {
            int ch = tid + (i & 3) * 256;
            int r = ch >> 4, c4 = (ch & 15) << 2, c8 = (ch & 15) << 3;
            if (i < 4) cpasync16(sb + (OFF_K0  + r * AKST + c4) * 4, kg + (size_t)r * 128 + c8);
            else       cpasync16(sb + (OFF_VN0 + r * AKST + c4) * 4, vg + (size_t)r * 128 + c8);
        }
        asm volatile("cp.async.commit_group;");
    }

    for (int kt = 0; kt < nkt; kt++) {
        asm volatile("cp.async.wait_group 0;");
        __syncthreads();   // tile kt ready; all threads done reading buf (kt+1)&1

        if (kt + 1 < nkt) {
            const __half* kg = k + base + (size_t)(kt + 1) * 64 * 128;
            const __half* vg = v + base + (size_t)(kt + 1) * 64 * 128;
            uint32_t Kd = sb + ((((kt + 1) & 1) ? OFF_K1  : OFF_K0))  * 4;
            uint32_t Vd = sb + ((((kt + 1) & 1) ? OFF_VN1 : OFF_VN0)) * 4;
#pragma unroll
            for (int i = 0; i < 8; i++) {
                int ch = tid + (i & 3) * 256;
                int r = ch >> 4, c4 = (ch & 15) << 2, c8 = (ch & 15) << 3;
                if (i < 4) cpasync16(Kd + (r * AKST + c4) * 4, kg + (size_t)r * 128 + c8);
                else       cpasync16(Vd + (r * AKST + c4) * 4, vg + (size_t)r * 128 + c8);
            }
            asm volatile("cp.async.commit_group;");
        }

        const uint32_t Kb = sb + (((kt & 1) ? OFF_K1  : OFF_K0))  * 4;
        const uint32_t Vn = sb + (((kt & 1) ? OFF_VN1 : OFF_VN0)) * 4;

        // ---- S = Q @ K^T (ldmatrix K fragments) ----
        float sc[8][4];
#pragma unroll
        for (int nt = 0; nt < 8; nt++)
#pragma unroll
            for (int j = 0; j < 4; j++) sc[nt][j] = 0.f;

#pragma unroll
        for (int kk = 0; kk < 8; kk++) {
#pragma unroll
            for (int ntp = 0; ntp < 4; ntp++) {
                uint32_t bf[4];
                ldsm_x4(bf, Kb + (constB + ntp * 16 * AKST + kk * 8) * 4);
                mma16(sc[2 * ntp],     qf[kk], bf);
                mma16(sc[2 * ntp + 1], qf[kk], bf + 2);
            }
        }

        // ---- causal mask ----
        if (kt >= 2 * qt) {
            int cbase = kt * 64 + 2 * t;
#pragma unroll
            for (int nt = 0; nt < 8; nt++) {
                int col = cbase + nt * 8;
                if (col     > row0g) sc[nt][0] = -CUDART_INF_F;
                if (col + 1 > row0g) sc[nt][1] = -CUDART_INF_F;
                if (col     > row1g) sc[nt][2] = -CUDART_INF_F;
                if (col + 1 > row1g) sc[nt][3] = -CUDART_INF_F;
            }
        }

        // ---- online softmax ----
        float rmax0 = -CUDART_INF_F, rmax1 = -CUDART_INF_F;
#pragma unroll
        for (int nt = 0; nt < 8; nt++) {
            rmax0 = fmaxf(rmax0, fmaxf(sc[nt][0], sc[nt][1]));
            rmax1 = fmaxf(rmax1, fmaxf(sc[nt][2], sc[nt][3]));
        }
        rmax0 = fmaxf(rmax0, __shfl_xor_sync(0xffffffffu, rmax0, 1, 4));
        rmax0 = fmaxf(rmax0, __shfl_xor_sync(0xffffffffu, rmax0, 2, 4));
        rmax1 = fmaxf(rmax1, __shfl_xor_sync(0xffffffffu, rmax1, 1, 4));
        rmax1 = fmaxf(rmax1, __shfl_xor_sync(0xffffffffu, rmax1, 2, 4));

        float mn0 = fmaxf(m0, rmax0);
        float mn1 = fmaxf(m1, rmax1);
        float fac0 = __expf(m0 - mn0);
        float fac1 = __expf(m1 - mn1);
        m0 = mn0; m1 = mn1;

        float rs0 = 0.f, rs1 = 0.f;
#pragma unroll
        for (int nt = 0; nt < 8; nt++) {
            float p0 = __expf(sc[nt][0] - mn0);
            float p1 = __expf(sc[nt][1] - mn0);
            float p2 = __expf(sc[nt][2] - mn1);
            float p3 = __expf(sc[nt][3] - mn1);
            sc[nt][0] = p0; sc[nt][1] = p1; sc[nt][2] = p2; sc[nt][3] = p3;
            rs0 += p0 + p1; rs1 += p2 + p3;
        }
        rs0 += __shfl_xor_sync(0xffffffffu, rs0, 1, 4);
        rs0 += __shfl_xor_sync(0xffffffffu, rs0, 2, 4);
        rs1 += __shfl_xor_sync(0xffffffffu, rs1, 1, 4);
        rs1 += __shfl_xor_sync(0xffffffffu, rs1, 2, 4);
        l0 = l0 * fac0 + rs0;
        l1 = l1 * fac1 + rs1;

#pragma unroll
        for (int nt = 0; nt < 16; nt++) {
            of[nt][0] *= fac0; of[nt][1] *= fac0;
            of[nt][2] *= fac1; of[nt][3] *= fac1;
        }

        // ---- O += P @ V : P packed from registers, V via ldmatrix.trans ----
#pragma unroll
        for (int kk = 0; kk < 4; kk++) {
            uint32_t ap[4];
            ap[0] = packh2(sc[2 * kk][0],     sc[2 * kk][1]);
            ap[1] = packh2(sc[2 * kk][2],     sc[2 * kk][3]);
            ap[2] = packh2(sc[2 * kk + 1][0], sc[2 * kk + 1][1]);
            ap[3] = packh2(sc[2 * kk + 1][2], sc[2 * kk + 1][3]);
#pragma unroll
            for (int ntp = 0; ntp < 8; ntp++) {
                uint32_t bf[4];
                ldsm_x4t(bf, Vn + (constA + kk * 16 * AKST + ntp * 8) * 4);
                mma16(of[2 * ntp],     ap, bf);
                mma16(of[2 * ntp + 1], ap, bf + 2);
            }
        }
    }

    // ---- epilogue: normalize, write half to [B,S,H*128] ----
    float inv0 = 1.0f / l0;
    float inv1 = 1.0f / l1;
    size_t orow0 = ((size_t)(b * S_ + row0g)) * 1536 + h * 128;
    size_t orow1 = ((size_t)(b * S_ + row1g)) * 1536 + h * 128;
#pragma unroll
    for (int nt = 0; nt < 16; nt++) {
        int col = nt * 8 + 2 * t;
        *(__half2*)&o[orow0 + col] = __floats2half2_rn(of[nt][0] * inv0, of[nt][1] * inv0);
        *(__half2*)&o[orow1 + col] = __floats2half2_rn(of[nt][2] * inv1, of[nt][3] * inv1);
    }
}

// ---------------- launch ----------------
extern "C" void kernel_launch(void* const* d_in, const int* in_sizes, int n_in,
                              void* d_out, int out_size)
{
    const float* x         = (const float*)d_in[0];
    const float* W_dkv     = (const float*)d_in[2];
    const float* b_dkv     = (const float*)d_in[3];
    const float* W_dq      = (const float*)d_in[4];
    const float* b_dq      = (const float*)d_in[5];
    const float* W_uk_nope = (const float*)d_in[6];
    const float* b_uk_nope = (const float*)d_in[7];
    const float* W_uv      = (const float*)d_in[8];
    const float* b_uv      = (const float*)d_in[9];
    const float* W_uq_nope = (const float*)d_in[10];
    const float* b_uq_nope = (const float*)d_in[11];
    const float* W_uq_rope = (const float*)d_in[12];
    const float* b_uq_rope = (const float*)d_in[13];
    const float* W_uk_rope = (const float*)d_in[14];
    const float* b_uk_rope = (const float*)d_in[15];
    const float* W_o       = (const float*)d_in[16];
    const float* b_o       = (const float*)d_in[17];
    float* out = (float*)d_out;

    __half *Cq, *Ckv, *q, *k, *vh, *o, *xh, *Wh;
    cudaGetSymbolAddress((void**)&Cq,  g_Cq);
    cudaGetSymbolAddress((void**)&Ckv, g_Ckv);
    cudaGetSymbolAddress((void**)&q,   g_q);
    cudaGetSymbolAddress((void**)&k,   g_k);
    cudaGetSymbolAddress((void**)&vh,  g_vh);
    cudaGetSymbolAddress((void**)&o,   g_o);
    cudaGetSymbolAddress((void**)&xh,  g_xh);
    cudaGetSymbolAddress((void**)&Wh,  g_Wh);

    cudaFuncSetAttribute(attn_f16, cudaFuncAttributeMaxDynamicSharedMemorySize, ATT_SMEM_BYTES);
    cudaFuncSetAttribute(gemm_f16_multi, cudaFuncAttributeMaxDynamicSharedMemorySize, MG_SMEM);

    dim3 t(256);
    init_freq_kernel<<<2, 192>>>();

    // convert x and all fp16-consumed weights
    CTasks ct;
    ct.src[0] = x;         ct.dst[0] = xh;
    ct.src[1] = W_uq_nope; ct.dst[1] = Wh + WR_UQN;
    ct.src[2] = W_uq_rope; ct.dst[2] = Wh + WR_UQR;
    ct.src[3] = W_uk_nope; ct.dst[3] = Wh + WR_UKN;
    ct.src[4] = W_uv;      ct.dst[4] = Wh + WR_UV;
    ct.src[5] = W_uk_rope; ct.dst[5] = Wh + WR_UKR;
    ct.src[6] = W_o;       ct.dst[6] = Wh + WR_O;
    ct.src[7] = W_dq;      ct.dst[7] = Wh + WR_DQ;
    ct.src[8] = W_dkv;     ct.dst[8] = Wh + WR_DKV;
    int counts[9] = {MROWS*768, 98304, 98304, 98304, 196608, 589824, 1179648, 98304, 98304};
    int acc4 = 0;
    for (int i = 0; i < 9; i++) { acc4 += counts[i] / 4; ct.end4[i] = acc4; }
    conv_half_kernel<<<(acc4 + 255) / 256, 256>>>(ct);

    // latent projections in fp16 (half outputs)
    GTasks gl;
    gl.n = 2;
    gl.nblocks = 128;
    gl.t[0] = { xh, Wh + WR_DQ,  b_dq,  Cq,  768, 6, 1, 0  };
    gl.t[1] = { xh, Wh + WR_DKV, b_dkv, Ckv, 768, 6, 1, 64 };
    gemm_f16_multi<<<128, t, MG_SMEM>>>(gl);

    // five up-projections fused (heavy-K k_rope first); epilogues do rope+scatter
    GTasks gt;
    gt.n = 5;
    gt.nblocks = 2304;
    gt.t[0] = { xh,  Wh + WR_UKR, b_uk_rope, k,   768, 4,  6, 0    };
    gt.t[1] = { Ckv, Wh + WR_UV,  b_uv,      vh,  128, 5, 12, 384  };
    gt.t[2] = { Cq,  Wh + WR_UQN, b_uq_nope, q,   128, 1,  6, 1152 };
    gt.t[3] = { Cq,  Wh + WR_UQR, b_uq_rope, q,   128, 2,  6, 1536 };
    gt.t[4] = { Ckv, Wh + WR_UKN, b_uk_nope, k,   128, 3,  6, 1920 };
    gemm_f16_multi<<<2304, t, MG_SMEM>>>(gt);

    // fp16 flash attention
    attn_f16<<<dim3(S_ / 128, B_ * H_), t, ATT_SMEM_BYTES>>>(q, k, vh, o);

    // output projection (fp32 result)
    GTasks go;
    go.n = 1;
    go.nblocks = 384;
    go.t[0] = { o, Wh + WR_O, b_o, out, 1536, 0, 6, 0 };
    gemm_f16_multi<<<384, t, MG_SMEM>>>(go);
}